// round 10
// baseline (speedup 1.0000x reference)
#include <cuda_runtime.h>
#include <cuda_fp16.h>
#include <cstdint>

#define NS   262144
#define C    128
#define KK   27
#define EPSF 1e-4f

#define CTA_M    256
#define PIPE     2
#define NSTAGE   KK                  // 27 stages: one k-offset, full cin=128
#define A_ROWB   256                 // bytes per A row (128 halves), XOR-swizzled
#define A_BYTES  (CTA_M * A_ROWB)    // 65536
#define W_COLB   288                 // bytes per W col (256B data + 32B pad)
#define W_BYTES  (C * W_COLB)        // 36864
#define DSMEM_TOTAL (PIPE * (A_BYTES + W_BYTES))   // 204800
#define NCTA     (NS / CTA_M)        // 1024

// ===================== scratch (device globals) =====================
__device__ __half g_h[NS * C];        // BN-ReLU output fp16 (conv gather source)
__device__ __half g_yh[NS * C];       // conv1 output, raw fp16
__device__ __half g_wt1[KK * C * C];  // W permuted: [k][col][128 halves]
__device__ __half g_wt2[KK * C * C];
__device__ int    g_idx[KK * NS];     // transposed rulebook: [k][site]
__device__ float  g_part[NCTA * 256]; // per-CTA BN partials
__device__ float  g_sum[C];
__device__ float  g_sumsq[C];
__device__ float  g_scale[C];
__device__ float  g_shift[C];

// ===================== helpers =====================
__device__ __forceinline__ uint32_t smem_u32(const void* p) {
    uint32_t a;
    asm("{ .reg .u64 t; cvta.to.shared.u64 t, %1; cvt.u32.u64 %0, t; }"
        : "=r"(a) : "l"(p));
    return a;
}

__device__ __forceinline__ void cp_async16(uint32_t dst, const void* src, uint32_t sz) {
    asm volatile("cp.async.cg.shared.global [%0], [%1], 16, %2;"
                 :: "r"(dst), "l"(src), "r"(sz) : "memory");
}
#define CP_COMMIT() asm volatile("cp.async.commit_group;" ::: "memory")
#define CP_WAIT(n)  asm volatile("cp.async.wait_group %0;" :: "n"(n) : "memory")

__device__ __forceinline__ void ldmatrix_x4(uint32_t* r, uint32_t addr) {
    asm volatile("ldmatrix.sync.aligned.m8n8.x4.shared.b16 {%0,%1,%2,%3}, [%4];"
                 : "=r"(r[0]), "=r"(r[1]), "=r"(r[2]), "=r"(r[3]) : "r"(addr));
}

__device__ __forceinline__ void mma_f16(float* c, const uint32_t* a,
                                        uint32_t b0, uint32_t b1) {
    asm volatile(
        "mma.sync.aligned.m16n8k16.row.col.f32.f16.f16.f32 "
        "{%0,%1,%2,%3}, {%4,%5,%6,%7}, {%8,%9}, {%0,%1,%2,%3};"
        : "+f"(c[0]), "+f"(c[1]), "+f"(c[2]), "+f"(c[3])
        : "r"(a[0]), "r"(a[1]), "r"(a[2]), "r"(a[3]), "r"(b0), "r"(b1));
}

// ===================== BN / prep kernels =====================
// float4, 32 rows/thread; writes block partials (no global atomics)
__global__ void bn_stats_kernel(const float4* __restrict__ x) {
    __shared__ float4 sh_s[256], sh_q[256];
    const int tid = threadIdx.x;
    const int c4  = tid & 31;
    const int ro  = tid >> 5;
    const size_t base = (size_t)blockIdx.x * 256;
    float4 s = make_float4(0.f, 0.f, 0.f, 0.f);
    float4 q = make_float4(0.f, 0.f, 0.f, 0.f);
    #pragma unroll 8
    for (int j = 0; j < 32; j++) {
        float4 v = x[(base + ro + j * 8) * 32 + c4];
        s.x += v.x; s.y += v.y; s.z += v.z; s.w += v.w;
        q.x += v.x * v.x; q.y += v.y * v.y; q.z += v.z * v.z; q.w += v.w * v.w;
    }
    sh_s[tid] = s; sh_q[tid] = q;
    __syncthreads();
    if (tid < C) {
        float ss = 0.f, qq = 0.f;
        const float* ps = (const float*)sh_s;
        const float* pq = (const float*)sh_q;
        #pragma unroll
        for (int r = 0; r < 8; r++) {
            ss += ps[r * 128 + tid];
            qq += pq[r * 128 + tid];
        }
        g_part[blockIdx.x * 256 + tid]       = ss;
        g_part[blockIdx.x * 256 + 128 + tid] = qq;
    }
}

// reduce partials into g_sum / g_sumsq
__global__ void reduce_stats_kernel() {
    const int col = blockIdx.x;      // 0..255 (0..127 sum, 128..255 sumsq)
    float s = 0.f;
    for (int cta = threadIdx.x; cta < NCTA; cta += 128)
        s += g_part[cta * 256 + col];
    __shared__ float sh[128];
    sh[threadIdx.x] = s;
    __syncthreads();
    for (int o = 64; o > 0; o >>= 1) {
        if (threadIdx.x < o) sh[threadIdx.x] += sh[threadIdx.x + o];
        __syncthreads();
    }
    if (threadIdx.x == 0) {
        if (col < 128) g_sum[col] = sh[0];
        else           g_sumsq[col - 128] = sh[0];
    }
}

__global__ void bn_finalize_kernel(const float* __restrict__ gamma,
                                   const float* __restrict__ beta) {
    int c = threadIdx.x;
    if (c < C) {
        float mu  = g_sum[c]   * (1.f / (float)NS);
        float var = g_sumsq[c] * (1.f / (float)NS) - mu * mu;
        float sc  = gamma[c] * rsqrtf(var + EPSF);
        g_scale[c] = sc;
        g_shift[c] = beta[c] - mu * sc;
    }
}

// BN + ReLU + fp16 pack, fp32 input (layer 1)
__global__ void bn_apply_pack_kernel(const float4* __restrict__ x,
                                     __half2* __restrict__ o) {
    int i  = blockIdx.x * blockDim.x + threadIdx.x;   // over NS*C/4
    int c4 = (i & 31) << 2;
    float4 v = x[i];
    float r0 = fmaxf(fmaf(v.x, g_scale[c4+0], g_shift[c4+0]), 0.f);
    float r1 = fmaxf(fmaf(v.y, g_scale[c4+1], g_shift[c4+1]), 0.f);
    float r2 = fmaxf(fmaf(v.z, g_scale[c4+2], g_shift[c4+2]), 0.f);
    float r3 = fmaxf(fmaf(v.w, g_scale[c4+3], g_shift[c4+3]), 0.f);
    o[i * 2 + 0] = __floats2half2_rn(r0, r1);
    o[i * 2 + 1] = __floats2half2_rn(r2, r3);
}

// BN + ReLU + fp16 pack, fp16 input (layer 2)
__global__ void bn_apply_pack_half_kernel(const uint4* __restrict__ x,
                                          uint4* __restrict__ o) {
    int i  = blockIdx.x * blockDim.x + threadIdx.x;   // over NS*C/8
    int c8 = (i & 15) << 3;
    uint4 v = x[i];
    uint4 r;
    const __half2* hv = (const __half2*)&v;
    __half2* hr = (__half2*)&r;
    #pragma unroll
    for (int j = 0; j < 4; j++) {
        float2 f = __half22float2(hv[j]);
        int c = c8 + j * 2;
        float a = fmaxf(fmaf(f.x, g_scale[c],     g_shift[c]),     0.f);
        float b = fmaxf(fmaf(f.y, g_scale[c + 1], g_shift[c + 1]), 0.f);
        hr[j] = __floats2half2_rn(a, b);
    }
    o[i] = r;
}

// Transpose + encode rulebook: g_idx[k][site] = mask ? (nbr*C)|signbit : 0
__global__ void prep_idx_kernel(const int* __restrict__ nbr_idx,
                                const int* __restrict__ nbr_mask) {
    __shared__ int sm[128 * KK];
    const int m0 = blockIdx.x * 128;
    for (int i = threadIdx.x; i < 128 * KK; i += 256) {
        int gi = m0 * KK + i;
        sm[i] = nbr_mask[gi] ? (int)((uint32_t)(nbr_idx[gi] * C) | 0x80000000u) : 0;
    }
    __syncthreads();
    for (int i = threadIdx.x; i < 128 * KK; i += 256) {
        int k = i >> 7, r = i & 127;
        g_idx[k * NS + m0 + r] = sm[r * KK + k];
    }
}

// W[k][cin][cout] -> g_wt[k][col][pos], pos 0..127 in B-fragment pair order:
// per 16-k group s, lane lc's LDS.64 at halves [lc*4,lc*4+4) yields
// k = 2lc,2lc+1 (b0) and 2lc+8,2lc+9 (b1).
__global__ void pack_w_kernel(const float* __restrict__ W,
                              __half* __restrict__ wt) {
    int o = blockIdx.x * blockDim.x + threadIdx.x;    // KK*C*C
    int pos = o & 127;
    int col = (o >> 7) & 127;
    int k   = o >> 14;
    int s = pos >> 4, q = pos & 15;
    int c = q >> 2,  d = q & 3;
    int krel = (d < 2) ? (2 * c + d) : (8 + 2 * c + (d - 2));
    int cin = s * 16 + krel;
    wt[o] = __float2half_rn(W[(k * C + cin) * C + col]);
}

// ===================== fp16 mma.sync gather-GEMM conv =====================
// OUT_HALF: write raw fp16 output (conv1); else fp32 (+residual)
template<bool OUT_HALF>
__global__ void __launch_bounds__(256, 1)
conv_mma_kernel(const __half* __restrict__ h,
                const int*    __restrict__ idxT,   // transposed rulebook
                const __half* __restrict__ wt,
                const float*  __restrict__ bias,
                const float*  __restrict__ residual,
                void*         __restrict__ outv,
                float*        __restrict__ stats_part)
{
    extern __shared__ char dsm[];
    __shared__ float s_bias[C];
    __shared__ float s_st[256];

    const int tid  = threadIdx.x;
    const int warp = tid >> 5;
    const int lane = tid & 31;
    const int m0   = blockIdx.x * CTA_M;

    const uint32_t smA_u = smem_u32(dsm);
    const uint32_t smW_u = smA_u + PIPE * A_BYTES;

    if (tid < C) s_bias[tid] = bias[tid];
    s_st[tid] = 0.f;
    __syncthreads();

    // warp tiling: 4 M-warps x 2 N-warps, warp tile 64x64
    const int mw = warp & 3;
    const int nw = warp >> 2;
    const int lr = lane >> 2;        // 0..7
    const int lc = lane & 3;         // 0..3
    // ldmatrix lane mapping
    const int gq = lane >> 3;
    const int gl = lane & 7;
    const int rowl = (gq & 1) * 8 + gl;
    const int ghi  = gq >> 1;

    float acc[4][8][4];
    #pragma unroll
    for (int a = 0; a < 4; a++)
        #pragma unroll
        for (int b = 0; b < 8; b++)
            #pragma unroll
            for (int q = 0; q < 4; q++) acc[a][b][q] = 0.f;

    const int wcol = tid & 127;
    const int whalf = tid >> 7;      // 0/1 : which 128B half of the col
    const int swA  = (tid & 7) << 4; // XOR swizzle term for own-row stores

    auto issue = [&](int k, int p) {
        // A gather: thread -> its row (256B, 16 x 16B chunks, swizzled)
        int v = idxT[k * NS + m0 + tid];
        uint32_t sz = (v < 0) ? 16u : 0u;
        const __half* src = h + (v & 0x7FFFFFFF);
        uint32_t dstrow = smA_u + p * A_BYTES + tid * A_ROWB;
        #pragma unroll
        for (int j = 0; j < 16; j++)
            cp_async16(dstrow + ((j << 4) ^ swA), src + j * 8, sz);
        // W copy (permuted fp16 in gmem): 128B per thread
        const __half* wsrc = wt + ((size_t)k * C + wcol) * 128 + whalf * 64;
        uint32_t wdst = smW_u + p * W_BYTES + wcol * W_COLB + whalf * 128;
        #pragma unroll
        for (int j = 0; j < 8; j++)
            cp_async16(wdst + j * 16, wsrc + j * 8, 16u);
        CP_COMMIT();
    };

    issue(0, 0);

    for (int st = 0; st < NSTAGE; st++) {
        const int p = st & 1;
        if (st + 1 < NSTAGE) { issue(st + 1, (st + 1) & 1); CP_WAIT(1); }
        else { CP_WAIT(0); }
        __syncthreads();

        const uint32_t Abase = smA_u + p * A_BYTES;
        const uint32_t Wbase = smW_u + p * W_BYTES +
                               (nw * 64 + lr) * W_COLB + lc * 8;

        #pragma unroll
        for (int s = 0; s < 8; s++) {
            uint32_t af[4][4];
            #pragma unroll
            for (int mf = 0; mf < 4; mf++) {
                int row = mw * 64 + mf * 16 + rowl;
                uint32_t addr = Abase + row * A_ROWB +
                                ((((s << 1) | ghi) ^ (row & 7)) << 4);
                ldmatrix_x4(af[mf], addr);
            }
            #pragma unroll
            for (int nf = 0; nf < 8; nf++) {
                uint32_t b0, b1;
                uint32_t baddr = Wbase + nf * (8 * W_COLB) + s * 32;
                asm volatile("ld.shared.v2.b32 {%0,%1}, [%2];"
                             : "=r"(b0), "=r"(b1) : "r"(baddr));
                #pragma unroll
                for (int mf = 0; mf < 4; mf++)
                    mma_f16(acc[mf][nf], af[mf], b0, b1);
            }
        }
        __syncthreads();
    }

    // ---- epilogue ----
    float st_s[8][2], st_q[8][2];
    #pragma unroll
    for (int nf = 0; nf < 8; nf++) {
        st_s[nf][0] = st_s[nf][1] = 0.f;
        st_q[nf][0] = st_q[nf][1] = 0.f;
    }

    #pragma unroll
    for (int mf = 0; mf < 4; mf++) {
        int row = m0 + mw * 64 + mf * 16 + lr;
        #pragma unroll
        for (int nf = 0; nf < 8; nf++) {
            int col = nw * 64 + nf * 8 + lc * 2;
            float2 v0, v1;
            v0.x = acc[mf][nf][0] + s_bias[col];
            v0.y = acc[mf][nf][1] + s_bias[col + 1];
            v1.x = acc[mf][nf][2] + s_bias[col];
            v1.y = acc[mf][nf][3] + s_bias[col + 1];
            if (!OUT_HALF && residual) {
                float2 r0v = *(const float2*)&residual[(size_t)row * C + col];
                float2 r1v = *(const float2*)&residual[(size_t)(row + 8) * C + col];
                v0.x += r0v.x; v0.y += r0v.y;
                v1.x += r1v.x; v1.y += r1v.y;
            }
            if (stats_part) {
                st_s[nf][0] += v0.x + v1.x;
                st_s[nf][1] += v0.y + v1.y;
                st_q[nf][0] += v0.x * v0.x + v1.x * v1.x;
                st_q[nf][1] += v0.y * v0.y + v1.y * v1.y;
            }
            if (OUT_HALF) {
                __half* oh = (__half*)outv;
                *(__half2*)&oh[(size_t)row * C + col]       = __floats2half2_rn(v0.x, v0.y);
                *(__half2*)&oh[(size_t)(row + 8) * C + col] = __floats2half2_rn(v1.x, v1.y);
            } else {
                float* of = (float*)outv;
                *(float2*)&of[(size_t)row * C + col]       = v0;
                *(float2*)&of[(size_t)(row + 8) * C + col] = v1;
            }
        }
    }

    if (stats_part) {
        #pragma unroll
        for (int nf = 0; nf < 8; nf++) {
            #pragma unroll
            for (int j = 0; j < 2; j++) {
                float s = st_s[nf][j], q = st_q[nf][j];
                #pragma unroll
                for (int m = 4; m <= 16; m <<= 1) {
                    s += __shfl_xor_sync(0xFFFFFFFFu, s, m);
                    q += __shfl_xor_sync(0xFFFFFFFFu, q, m);
                }
                if (lr == 0) {
                    int col = nw * 64 + nf * 8 + lc * 2 + j;
                    atomicAdd(&s_st[col],       s);
                    atomicAdd(&s_st[col + 128], q);
                }
            }
        }
        __syncthreads();
        stats_part[blockIdx.x * 256 + tid] = s_st[tid];
    }
}

// ===================== launch =====================
extern "C" void kernel_launch(void* const* d_in, const int* in_sizes, int n_in,
                              void* d_out, int out_size)
{
    const float* features = (const float*)d_in[0];
    const int*   nbr_idx  = (const int*)  d_in[1];
    const int*   nbr_mask = (const int*)  d_in[2];
    const float* gamma1   = (const float*)d_in[3];
    const float* beta1    = (const float*)d_in[4];
    const float* W1       = (const float*)d_in[5];
    const float* bias1    = (const float*)d_in[6];
    const float* gamma2   = (const float*)d_in[7];
    const float* beta2    = (const float*)d_in[8];
    const float* W2       = (const float*)d_in[9];
    const float* bias2    = (const float*)d_in[10];
    float* out = (float*)d_out;

    __half *h_ptr, *yh_ptr, *wt1_ptr, *wt2_ptr;
    float *part_ptr;
    int *idx_ptr;
    cudaGetSymbolAddress((void**)&h_ptr,    g_h);
    cudaGetSymbolAddress((void**)&yh_ptr,   g_yh);
    cudaGetSymbolAddress((void**)&wt1_ptr,  g_wt1);
    cudaGetSymbolAddress((void**)&wt2_ptr,  g_wt2);
    cudaGetSymbolAddress((void**)&part_ptr, g_part);
    cudaGetSymbolAddress((void**)&idx_ptr,  g_idx);

    cudaFuncSetAttribute(conv_mma_kernel<true>,
                         cudaFuncAttributeMaxDynamicSharedMemorySize, DSMEM_TOTAL);
    cudaFuncSetAttribute(conv_mma_kernel<false>,
                         cudaFuncAttributeMaxDynamicSharedMemorySize, DSMEM_TOTAL);

    const int stats_grid  = NS / 256;
    const int apply_grid  = (NS * C / 4) / 256;
    const int applyh_grid = (NS * C / 8) / 256;
    const int packw_grid  = (KK * C * C) / 256;

    // one-shot prep
    pack_w_kernel<<<packw_grid, 256>>>(W1, wt1_ptr);
    pack_w_kernel<<<packw_grid, 256>>>(W2, wt2_ptr);
    prep_idx_kernel<<<NS / 128, 256>>>(nbr_idx, nbr_mask);

    // ---- layer 1 ----
    bn_stats_kernel<<<stats_grid, 256>>>((const float4*)features);
    reduce_stats_kernel<<<256, 128>>>();
    bn_finalize_kernel<<<1, 128>>>(gamma1, beta1);
    bn_apply_pack_kernel<<<apply_grid, 256>>>((const float4*)features, (__half2*)h_ptr);
    conv_mma_kernel<true><<<NCTA, 256, DSMEM_TOTAL>>>(
        h_ptr, idx_ptr, wt1_ptr, bias1, nullptr, yh_ptr, part_ptr);

    // ---- layer 2: stats from conv1 epilogue ----
    reduce_stats_kernel<<<256, 128>>>();
    bn_finalize_kernel<<<1, 128>>>(gamma2, beta2);
    bn_apply_pack_half_kernel<<<applyh_grid, 256>>>((const uint4*)yh_ptr, (uint4*)h_ptr);
    conv_mma_kernel<false><<<NCTA, 256, DSMEM_TOTAL>>>(
        h_ptr, idx_ptr, wt2_ptr, bias2, features, out, nullptr);
}

// round 11
// speedup vs baseline: 1.0104x; 1.0104x over previous
#include <cuda_runtime.h>
#include <cuda_fp16.h>
#include <cstdint>

#define NS   262144
#define C    128
#define KK   27
#define EPSF 1e-4f

#define CTA_M    256
#define PIPE     3
#define NSTAGE   (KK * 2)            // 54 stages: k x 2 cin-chunks of 64
#define A_ROWB   128                 // bytes per A row (64 halves), XOR-swizzled
#define A_BYTES  (CTA_M * A_ROWB)    // 32768
#define W_STRIDEB 160                // bytes per W col (64 halves + pad)
#define W_BYTES  (C * W_STRIDEB)     // 20480
#define DSMEM_TOTAL (PIPE * (A_BYTES + W_BYTES))   // 159744
#define NCTA     (NS / CTA_M)        // 1024

// ===================== scratch (device globals) =====================
__device__ __half g_h[NS * C];        // BN-ReLU output fp16 (conv gather source)
__device__ __half g_yh[NS * C];       // conv1 output, raw fp16
__device__ __half g_wt1[KK * C * C];  // W permuted to B-fragment layout
__device__ __half g_wt2[KK * C * C];
__device__ float  g_part[NCTA * 256]; // per-CTA BN partials [cta][sum(128),sumsq(128)]
__device__ float  g_scale[C];
__device__ float  g_shift[C];

// ===================== helpers =====================
__device__ __forceinline__ uint32_t smem_u32(const void* p) {
    uint32_t a;
    asm("{ .reg .u64 t; cvta.to.shared.u64 t, %1; cvt.u32.u64 %0, t; }"
        : "=r"(a) : "l"(p));
    return a;
}

__device__ __forceinline__ void cp_async16(uint32_t dst, const void* src, uint32_t sz) {
    asm volatile("cp.async.cg.shared.global [%0], [%1], 16, %2;"
                 :: "r"(dst), "l"(src), "r"(sz) : "memory");
}
#define CP_COMMIT() asm volatile("cp.async.commit_group;" ::: "memory")
#define CP_WAIT(n)  asm volatile("cp.async.wait_group %0;" :: "n"(n) : "memory")

__device__ __forceinline__ void ldmatrix_x4(uint32_t* r, uint32_t addr) {
    asm volatile("ldmatrix.sync.aligned.m8n8.x4.shared.b16 {%0,%1,%2,%3}, [%4];"
                 : "=r"(r[0]), "=r"(r[1]), "=r"(r[2]), "=r"(r[3]) : "r"(addr));
}

__device__ __forceinline__ void mma_f16(float* c, const uint32_t* a,
                                        uint32_t b0, uint32_t b1) {
    asm volatile(
        "mma.sync.aligned.m16n8k16.row.col.f32.f16.f16.f32 "
        "{%0,%1,%2,%3}, {%4,%5,%6,%7}, {%8,%9}, {%0,%1,%2,%3};"
        : "+f"(c[0]), "+f"(c[1]), "+f"(c[2]), "+f"(c[3])
        : "r"(a[0]), "r"(a[1]), "r"(a[2]), "r"(a[3]), "r"(b0), "r"(b1));
}

// ===================== BN / prep kernels =====================
// float4, 32 rows/thread; writes block partials (no global atomics)
__global__ void bn_stats_kernel(const float4* __restrict__ x) {
    __shared__ float4 sh_s[256], sh_q[256];
    const int tid = threadIdx.x;
    const int c4  = tid & 31;
    const int ro  = tid >> 5;
    const size_t base = (size_t)blockIdx.x * 256;
    float4 s = make_float4(0.f, 0.f, 0.f, 0.f);
    float4 q = make_float4(0.f, 0.f, 0.f, 0.f);
    #pragma unroll 8
    for (int j = 0; j < 32; j++) {
        float4 v = x[(base + ro + j * 8) * 32 + c4];
        s.x += v.x; s.y += v.y; s.z += v.z; s.w += v.w;
        q.x += v.x * v.x; q.y += v.y * v.y; q.z += v.z * v.z; q.w += v.w * v.w;
    }
    sh_s[tid] = s; sh_q[tid] = q;
    __syncthreads();
    if (tid < C) {
        float ss = 0.f, qq = 0.f;
        const float* ps = (const float*)sh_s;
        const float* pq = (const float*)sh_q;
        #pragma unroll
        for (int r = 0; r < 8; r++) {
            ss += ps[r * 128 + tid];
            qq += pq[r * 128 + tid];
        }
        g_part[blockIdx.x * 256 + tid]       = ss;
        g_part[blockIdx.x * 256 + 128 + tid] = qq;
    }
}

// reduce partials + compute scale/shift, one block per channel
__global__ void reduce_finalize_kernel(const float* __restrict__ gamma,
                                       const float* __restrict__ beta) {
    const int c = blockIdx.x;        // 0..127
    float s = 0.f, q = 0.f;
    for (int cta = threadIdx.x; cta < NCTA; cta += 128) {
        s += g_part[cta * 256 + c];
        q += g_part[cta * 256 + 128 + c];
    }
    __shared__ float sh_s[128], sh_q[128];
    sh_s[threadIdx.x] = s; sh_q[threadIdx.x] = q;
    __syncthreads();
    for (int o = 64; o > 0; o >>= 1) {
        if (threadIdx.x < o) {
            sh_s[threadIdx.x] += sh_s[threadIdx.x + o];
            sh_q[threadIdx.x] += sh_q[threadIdx.x + o];
        }
        __syncthreads();
    }
    if (threadIdx.x == 0) {
        float mu  = sh_s[0] * (1.f / (float)NS);
        float var = sh_q[0] * (1.f / (float)NS) - mu * mu;
        float sc  = gamma[c] * rsqrtf(var + EPSF);
        g_scale[c] = sc;
        g_shift[c] = beta[c] - mu * sc;
    }
}

// BN + ReLU + fp16 pack, fp32 input (layer 1)
__global__ void bn_apply_pack_kernel(const float4* __restrict__ x,
                                     __half2* __restrict__ o) {
    int i  = blockIdx.x * blockDim.x + threadIdx.x;   // over NS*C/4
    int c4 = (i & 31) << 2;
    float4 v = x[i];
    float r0 = fmaxf(fmaf(v.x, g_scale[c4+0], g_shift[c4+0]), 0.f);
    float r1 = fmaxf(fmaf(v.y, g_scale[c4+1], g_shift[c4+1]), 0.f);
    float r2 = fmaxf(fmaf(v.z, g_scale[c4+2], g_shift[c4+2]), 0.f);
    float r3 = fmaxf(fmaf(v.w, g_scale[c4+3], g_shift[c4+3]), 0.f);
    o[i * 2 + 0] = __floats2half2_rn(r0, r1);
    o[i * 2 + 1] = __floats2half2_rn(r2, r3);
}

// BN + ReLU + fp16 pack, fp16 input (layer 2)
__global__ void bn_apply_pack_half_kernel(const uint4* __restrict__ x,
                                          uint4* __restrict__ o) {
    int i  = blockIdx.x * blockDim.x + threadIdx.x;   // over NS*C/8
    int c8 = (i & 15) << 3;
    uint4 v = x[i];
    uint4 r;
    const __half2* hv = (const __half2*)&v;
    __half2* hr = (__half2*)&r;
    #pragma unroll
    for (int j = 0; j < 4; j++) {
        float2 f = __half22float2(hv[j]);
        int c = c8 + j * 2;
        float a = fmaxf(fmaf(f.x, g_scale[c],     g_shift[c]),     0.f);
        float b = fmaxf(fmaf(f.y, g_scale[c + 1], g_shift[c + 1]), 0.f);
        hr[j] = __floats2half2_rn(a, b);
    }
    o[i] = r;
}

// Both W tensors in one launch.
// W[k][cin][cout] -> g_wt[(k*2+ch)][col][pos] (B-fragment pair layout)
__global__ void pack_w_kernel(const float* __restrict__ W1,
                              const float* __restrict__ W2) {
    int g = blockIdx.x * blockDim.x + threadIdx.x;    // 2*KK*C*C
    const float* W = (g < KK * C * C) ? W1 : W2;
    __half* wt     = (g < KK * C * C) ? g_wt1 : g_wt2;
    int o = (g < KK * C * C) ? g : g - KK * C * C;
    int pos = o & 63;
    int col = (o >> 6) & 127;
    int kc  = o >> 13;
    int ch  = kc & 1;
    int k   = kc >> 1;
    int s = pos >> 4, q = pos & 15;
    int c = q >> 2,  d = q & 3;
    int krel = (d < 2) ? (2 * c + d) : (8 + 2 * c + (d - 2));
    int cin = ch * 64 + s * 16 + krel;
    wt[o] = __float2half_rn(W[(k * C + cin) * C + col]);
}

// ===================== fp16 mma.sync gather-GEMM conv =====================
// OUT_HALF: write raw fp16 output (conv1); else fp32 (+residual)
template<bool OUT_HALF>
__global__ void __launch_bounds__(256, 1)
conv_mma_kernel(const __half* __restrict__ h,
                const int*    __restrict__ nbr_idx,
                const int*    __restrict__ nbr_mask,
                const __half* __restrict__ wt,
                const float*  __restrict__ bias,
                const float*  __restrict__ residual,
                void*         __restrict__ outv,
                float*        __restrict__ stats_part)
{
    extern __shared__ char dsm[];
    __shared__ int   s_idx[CTA_M * KK];
    __shared__ float s_bias[C];
    __shared__ float s_st[256];

    const int tid  = threadIdx.x;
    const int warp = tid >> 5;
    const int lane = tid & 31;
    const int m0   = blockIdx.x * CTA_M;

    const uint32_t smA_u = smem_u32(dsm);
    const uint32_t smW_u = smA_u + PIPE * A_BYTES;

    for (int i = tid; i < CTA_M * KK; i += 256) {
        int gi = m0 * KK + i;
        s_idx[i] = nbr_mask[gi] ? (int)((uint32_t)(nbr_idx[gi] * C) | 0x80000000u) : 0;
    }
    if (tid < C) s_bias[tid] = bias[tid];
    s_st[tid] = 0.f;
    __syncthreads();

    // warp tiling: 4 M-warps x 2 N-warps, warp tile 64x64
    const int mw = warp & 3;
    const int nw = warp >> 2;
    const int lr = lane >> 2;        // 0..7
    const int lc = lane & 3;         // 0..3
    // ldmatrix lane mapping
    const int gq = lane >> 3;
    const int gl = lane & 7;
    const int rowl = (gq & 1) * 8 + gl;
    const int ghi  = gq >> 1;

    float acc[4][8][4];
    #pragma unroll
    for (int a = 0; a < 4; a++)
        #pragma unroll
        for (int b = 0; b < 8; b++)
            #pragma unroll
            for (int q = 0; q < 4; q++) acc[a][b][q] = 0.f;

    const int wcol = tid & 127;
    const int wjb  = tid >> 7;
    const int swA  = (tid & 7) << 4;

    auto issue = [&](int st, int p) {
        const int k  = st >> 1;
        const int ch = st & 1;
        int v = s_idx[tid * KK + k];
        uint32_t sz = (v < 0) ? 16u : 0u;
        const __half* src = h + (v & 0x7FFFFFFF) + ch * 64;
        uint32_t dstrow = smA_u + p * A_BYTES + tid * A_ROWB;
        #pragma unroll
        for (int j = 0; j < 8; j++)
            cp_async16(dstrow + ((j << 4) ^ swA), src + j * 8, sz);
        const __half* wsrc = wt + ((size_t)(k * 2 + ch) * C + wcol) * 64 + wjb * 32;
        uint32_t wdst = smW_u + p * W_BYTES + wcol * W_STRIDEB + wjb * 64;
        #pragma unroll
        for (int j = 0; j < 4; j++)
            cp_async16(wdst + j * 16, wsrc + j * 8, 16u);
        CP_COMMIT();
    };

    issue(0, 0);
    issue(1, 1);

    for (int st = 0; st < NSTAGE; st++) {
        const int p = st % PIPE;
        if (st + 2 < NSTAGE) { issue(st + 2, (st + 2) % PIPE); CP_WAIT(2); }
        else if (st + 1 < NSTAGE) { CP_WAIT(1); }
        else { CP_WAIT(0); }
        __syncthreads();

        const uint32_t Abase = smA_u + p * A_BYTES;
        const uint32_t Wbase = smW_u + p * W_BYTES +
                               (nw * 64 + lr) * W_STRIDEB + lc * 8;

        #pragma unroll
        for (int s = 0; s < 4; s++) {
            uint32_t af[4][4];
            #pragma unroll
            for (int mf = 0; mf < 4; mf++) {
                int row = mw * 64 + mf * 16 + rowl;
                uint32_t addr = Abase + row * A_ROWB +
                                ((((s << 1) | ghi) ^ (row & 7)) << 4);
                ldmatrix_x4(af[mf], addr);
            }
            #pragma unroll
            for (int nf = 0; nf < 8; nf++) {
                uint32_t b0, b1;
                uint32_t baddr = Wbase + nf * (8 * W_STRIDEB) + s * 32;
                asm volatile("ld.shared.v2.b32 {%0,%1}, [%2];"
                             : "=r"(b0), "=r"(b1) : "r"(baddr));
                #pragma unroll
                for (int mf = 0; mf < 4; mf++)
                    mma_f16(acc[mf][nf], af[mf], b0, b1);
            }
        }
        __syncthreads();
    }

    // ---- epilogue ----
    float st_s[8][2], st_q[8][2];
    #pragma unroll
    for (int nf = 0; nf < 8; nf++) {
        st_s[nf][0] = st_s[nf][1] = 0.f;
        st_q[nf][0] = st_q[nf][1] = 0.f;
    }

    #pragma unroll
    for (int mf = 0; mf < 4; mf++) {
        int row = m0 + mw * 64 + mf * 16 + lr;
        #pragma unroll
        for (int nf = 0; nf < 8; nf++) {
            int col = nw * 64 + nf * 8 + lc * 2;
            float2 v0, v1;
            v0.x = acc[mf][nf][0] + s_bias[col];
            v0.y = acc[mf][nf][1] + s_bias[col + 1];
            v1.x = acc[mf][nf][2] + s_bias[col];
            v1.y = acc[mf][nf][3] + s_bias[col + 1];
            if (!OUT_HALF && residual) {
                float2 r0v = *(const float2*)&residual[(size_t)row * C + col];
                float2 r1v = *(const float2*)&residual[(size_t)(row + 8) * C + col];
                v0.x += r0v.x; v0.y += r0v.y;
                v1.x += r1v.x; v1.y += r1v.y;
            }
            if (stats_part) {
                st_s[nf][0] += v0.x + v1.x;
                st_s[nf][1] += v0.y + v1.y;
                st_q[nf][0] += v0.x * v0.x + v1.x * v1.x;
                st_q[nf][1] += v0.y * v0.y + v1.y * v1.y;
            }
            if (OUT_HALF) {
                __half* oh = (__half*)outv;
                *(__half2*)&oh[(size_t)row * C + col]       = __floats2half2_rn(v0.x, v0.y);
                *(__half2*)&oh[(size_t)(row + 8) * C + col] = __floats2half2_rn(v1.x, v1.y);
            } else {
                float* of = (float*)outv;
                *(float2*)&of[(size_t)row * C + col]       = v0;
                *(float2*)&of[(size_t)(row + 8) * C + col] = v1;
            }
        }
    }

    if (stats_part) {
        #pragma unroll
        for (int nf = 0; nf < 8; nf++) {
            #pragma unroll
            for (int j = 0; j < 2; j++) {
                float s = st_s[nf][j], q = st_q[nf][j];
                #pragma unroll
                for (int m = 4; m <= 16; m <<= 1) {
                    s += __shfl_xor_sync(0xFFFFFFFFu, s, m);
                    q += __shfl_xor_sync(0xFFFFFFFFu, q, m);
                }
                if (lr == 0) {
                    int col = nw * 64 + nf * 8 + lc * 2 + j;
                    atomicAdd(&s_st[col],       s);
                    atomicAdd(&s_st[col + 128], q);
                }
            }
        }
        __syncthreads();
        stats_part[blockIdx.x * 256 + tid] = s_st[tid];
    }
}

// ===================== launch =====================
extern "C" void kernel_launch(void* const* d_in, const int* in_sizes, int n_in,
                              void* d_out, int out_size)
{
    const float* features = (const float*)d_in[0];
    const int*   nbr_idx  = (const int*)  d_in[1];
    const int*   nbr_mask = (const int*)  d_in[2];
    const float* gamma1   = (const float*)d_in[3];
    const float* beta1    = (const float*)d_in[4];
    const float* W1       = (const float*)d_in[5];
    const float* bias1    = (const float*)d_in[6];
    const float* gamma2   = (const float*)d_in[7];
    const float* beta2    = (const float*)d_in[8];
    const float* W2       = (const float*)d_in[9];
    const float* bias2    = (const float*)d_in[10];
    float* out = (float*)d_out;

    __half *h_ptr, *yh_ptr, *wt1_ptr, *wt2_ptr;
    float *part_ptr;
    cudaGetSymbolAddress((void**)&h_ptr,    g_h);
    cudaGetSymbolAddress((void**)&yh_ptr,   g_yh);
    cudaGetSymbolAddress((void**)&wt1_ptr,  g_wt1);
    cudaGetSymbolAddress((void**)&wt2_ptr,  g_wt2);
    cudaGetSymbolAddress((void**)&part_ptr, g_part);

    cudaFuncSetAttribute(conv_mma_kernel<true>,
                         cudaFuncAttributeMaxDynamicSharedMemorySize, DSMEM_TOTAL);
    cudaFuncSetAttribute(conv_mma_kernel<false>,
                         cudaFuncAttributeMaxDynamicSharedMemorySize, DSMEM_TOTAL);

    const int stats_grid  = NS / 256;
    const int apply_grid  = (NS * C / 4) / 256;
    const int applyh_grid = (NS * C / 8) / 256;
    const int packw_grid  = (2 * KK * C * C) / 256;

    pack_w_kernel<<<packw_grid, 256>>>(W1, W2);

    // ---- layer 1 ----
    bn_stats_kernel<<<stats_grid, 256>>>((const float4*)features);
    reduce_finalize_kernel<<<128, 128>>>(gamma1, beta1);
    bn_apply_pack_kernel<<<apply_grid, 256>>>((const float4*)features, (__half2*)h_ptr);
    conv_mma_kernel<true><<<NCTA, 256, DSMEM_TOTAL>>>(
        h_ptr, nbr_idx, nbr_mask, wt1_ptr, bias1, nullptr, yh_ptr, part_ptr);

    // ---- layer 2: stats from conv1 epilogue ----
    reduce_finalize_kernel<<<128, 128>>>(gamma2, beta2);
    bn_apply_pack_half_kernel<<<applyh_grid, 256>>>((const uint4*)yh_ptr, (uint4*)h_ptr);
    conv_mma_kernel<false><<<NCTA, 256, DSMEM_TOTAL>>>(
        h_ptr, nbr_idx, nbr_mask, wt2_ptr, bias2, features, out, nullptr);
}

// round 12
// speedup vs baseline: 1.0203x; 1.0097x over previous
#include <cuda_runtime.h>
#include <cuda_fp16.h>
#include <cstdint>

#define NS   262144
#define C    128
#define KK   27
#define EPSF 1e-4f

#define CTA_M    256
#define PIPE     3
#define NSTAGE   (KK * 2)            // 54 stages: k x 2 cin-chunks of 64
#define A_ROWB   128                 // bytes per A row (64 halves), XOR-swizzled
#define A_BYTES  (CTA_M * A_ROWB)    // 32768
#define W_STRIDEB 160                // bytes per W col (64 halves + pad)
#define W_BYTES  (C * W_STRIDEB)     // 20480
#define DSMEM_TOTAL (PIPE * (A_BYTES + W_BYTES))   // 159744
#define NCTA     (NS / CTA_M)        // 1024

// ===================== scratch (device globals) =====================
__device__ __half g_h[NS * C];        // BN-ReLU output fp16 (conv gather source)
__device__ __half g_yh[NS * C];       // conv1 output, raw fp16
__device__ __half g_wt1[KK * C * C];  // W permuted to B-fragment layout
__device__ __half g_wt2[KK * C * C];
__device__ float  g_part[NCTA * 256]; // per-CTA BN partials [cta][sum(128),sumsq(128)]
__device__ float  g_scale[C];
__device__ float  g_shift[C];

// ===================== helpers =====================
__device__ __forceinline__ uint32_t smem_u32(const void* p) {
    uint32_t a;
    asm("{ .reg .u64 t; cvta.to.shared.u64 t, %1; cvt.u32.u64 %0, t; }"
        : "=r"(a) : "l"(p));
    return a;
}

__device__ __forceinline__ void cp_async16(uint32_t dst, const void* src, uint32_t sz) {
    asm volatile("cp.async.cg.shared.global [%0], [%1], 16, %2;"
                 :: "r"(dst), "l"(src), "r"(sz) : "memory");
}
#define CP_COMMIT() asm volatile("cp.async.commit_group;" ::: "memory")
#define CP_WAIT(n)  asm volatile("cp.async.wait_group %0;" :: "n"(n) : "memory")

__device__ __forceinline__ void ldmatrix_x4(uint32_t* r, uint32_t addr) {
    asm volatile("ldmatrix.sync.aligned.m8n8.x4.shared.b16 {%0,%1,%2,%3}, [%4];"
                 : "=r"(r[0]), "=r"(r[1]), "=r"(r[2]), "=r"(r[3]) : "r"(addr));
}

__device__ __forceinline__ void mma_f16(float* c, const uint32_t* a,
                                        uint32_t b0, uint32_t b1) {
    asm volatile(
        "mma.sync.aligned.m16n8k16.row.col.f32.f16.f16.f32 "
        "{%0,%1,%2,%3}, {%4,%5,%6,%7}, {%8,%9}, {%0,%1,%2,%3};"
        : "+f"(c[0]), "+f"(c[1]), "+f"(c[2]), "+f"(c[3])
        : "r"(a[0]), "r"(a[1]), "r"(a[2]), "r"(a[3]), "r"(b0), "r"(b1));
}

// ===================== BN / prep kernels =====================
// float4, 32 rows/thread; writes block partials (no global atomics)
__global__ void bn_stats_kernel(const float4* __restrict__ x) {
    __shared__ float4 sh_s[256], sh_q[256];
    const int tid = threadIdx.x;
    const int c4  = tid & 31;
    const int ro  = tid >> 5;
    const size_t base = (size_t)blockIdx.x * 256;
    float4 s = make_float4(0.f, 0.f, 0.f, 0.f);
    float4 q = make_float4(0.f, 0.f, 0.f, 0.f);
    #pragma unroll 8
    for (int j = 0; j < 32; j++) {
        float4 v = x[(base + ro + j * 8) * 32 + c4];
        s.x += v.x; s.y += v.y; s.z += v.z; s.w += v.w;
        q.x += v.x * v.x; q.y += v.y * v.y; q.z += v.z * v.z; q.w += v.w * v.w;
    }
    sh_s[tid] = s; sh_q[tid] = q;
    __syncthreads();
    if (tid < C) {
        float ss = 0.f, qq = 0.f;
        const float* ps = (const float*)sh_s;
        const float* pq = (const float*)sh_q;
        #pragma unroll
        for (int r = 0; r < 8; r++) {
            ss += ps[r * 128 + tid];
            qq += pq[r * 128 + tid];
        }
        g_part[blockIdx.x * 256 + tid]       = ss;
        g_part[blockIdx.x * 256 + 128 + tid] = qq;
    }
}

// reduce partials + compute scale/shift, one block per channel
__global__ void reduce_finalize_kernel(const float* __restrict__ gamma,
                                       const float* __restrict__ beta) {
    const int c = blockIdx.x;        // 0..127
    float s = 0.f, q = 0.f;
    for (int cta = threadIdx.x; cta < NCTA; cta += 128) {
        s += g_part[cta * 256 + c];
        q += g_part[cta * 256 + 128 + c];
    }
    __shared__ float sh_s[128], sh_q[128];
    sh_s[threadIdx.x] = s; sh_q[threadIdx.x] = q;
    __syncthreads();
    for (int o = 64; o > 0; o >>= 1) {
        if (threadIdx.x < o) {
            sh_s[threadIdx.x] += sh_s[threadIdx.x + o];
            sh_q[threadIdx.x] += sh_q[threadIdx.x + o];
        }
        __syncthreads();
    }
    if (threadIdx.x == 0) {
        float mu  = sh_s[0] * (1.f / (float)NS);
        float var = sh_q[0] * (1.f / (float)NS) - mu * mu;
        float sc  = gamma[c] * rsqrtf(var + EPSF);
        g_scale[c] = sc;
        g_shift[c] = beta[c] - mu * sc;
    }
}

// BN + ReLU + fp16 pack, fp32 input (layer 1).
// Channel-quad fixed per thread; scale/shift loaded once, 32 rows streamed.
__global__ void bn_apply_pack_kernel(const float4* __restrict__ x,
                                     uint2* __restrict__ o) {
    const int tid = threadIdx.x;
    const int c4  = tid & 31;              // float4 column
    const int ro  = tid >> 5;              // 0..7
    const size_t base = (size_t)blockIdx.x * 256;
    const float s0 = g_scale[c4 * 4 + 0], s1 = g_scale[c4 * 4 + 1];
    const float s2 = g_scale[c4 * 4 + 2], s3 = g_scale[c4 * 4 + 3];
    const float t0 = g_shift[c4 * 4 + 0], t1 = g_shift[c4 * 4 + 1];
    const float t2 = g_shift[c4 * 4 + 2], t3 = g_shift[c4 * 4 + 3];
    #pragma unroll 8
    for (int j = 0; j < 32; j++) {
        size_t row = base + ro + j * 8;
        float4 v = x[row * 32 + c4];
        float r0 = fmaxf(fmaf(v.x, s0, t0), 0.f);
        float r1 = fmaxf(fmaf(v.y, s1, t1), 0.f);
        float r2 = fmaxf(fmaf(v.z, s2, t2), 0.f);
        float r3 = fmaxf(fmaf(v.w, s3, t3), 0.f);
        __half2 h0 = __floats2half2_rn(r0, r1);
        __half2 h1 = __floats2half2_rn(r2, r3);
        uint2 w;
        w.x = *reinterpret_cast<uint32_t*>(&h0);
        w.y = *reinterpret_cast<uint32_t*>(&h1);
        o[row * 32 + c4] = w;
    }
}

// BN + ReLU + fp16 pack, fp16 input (layer 2).
// Channel-octet fixed per thread; scale/shift loaded once, 16 rows streamed.
__global__ void bn_apply_pack_half_kernel(const uint4* __restrict__ x,
                                          uint4* __restrict__ o) {
    const int tid = threadIdx.x;
    const int c8  = tid & 15;              // uint4 column (8 halves)
    const int ro  = tid >> 4;              // 0..15
    const size_t base = (size_t)blockIdx.x * 256;
    float sc[8], sf[8];
    #pragma unroll
    for (int j = 0; j < 8; j++) {
        sc[j] = g_scale[c8 * 8 + j];
        sf[j] = g_shift[c8 * 8 + j];
    }
    #pragma unroll 4
    for (int j = 0; j < 16; j++) {
        size_t row = base + ro + j * 16;
        uint4 v = x[row * 16 + c8];
        uint4 r;
        const __half2* hv = (const __half2*)&v;
        __half2* hr = (__half2*)&r;
        #pragma unroll
        for (int p = 0; p < 4; p++) {
            float2 f = __half22float2(hv[p]);
            float a = fmaxf(fmaf(f.x, sc[p * 2],     sf[p * 2]),     0.f);
            float b = fmaxf(fmaf(f.y, sc[p * 2 + 1], sf[p * 2 + 1]), 0.f);
            hr[p] = __floats2half2_rn(a, b);
        }
        o[row * 16 + c8] = r;
    }
}

// Both W tensors in one launch.
// W[k][cin][cout] -> g_wt[(k*2+ch)][col][pos] (B-fragment pair layout)
__global__ void pack_w_kernel(const float* __restrict__ W1,
                              const float* __restrict__ W2) {
    int g = blockIdx.x * blockDim.x + threadIdx.x;    // 2*KK*C*C
    const float* W = (g < KK * C * C) ? W1 : W2;
    __half* wt     = (g < KK * C * C) ? g_wt1 : g_wt2;
    int o = (g < KK * C * C) ? g : g - KK * C * C;
    int pos = o & 63;
    int col = (o >> 6) & 127;
    int kc  = o >> 13;
    int ch  = kc & 1;
    int k   = kc >> 1;
    int s = pos >> 4, q = pos & 15;
    int c = q >> 2,  d = q & 3;
    int krel = (d < 2) ? (2 * c + d) : (8 + 2 * c + (d - 2));
    int cin = ch * 64 + s * 16 + krel;
    wt[o] = __float2half_rn(W[(k * C + cin) * C + col]);
}

// ===================== fp16 mma.sync gather-GEMM conv =====================
// OUT_HALF: write raw fp16 output (conv1); else fp32 (+residual)
template<bool OUT_HALF>
__global__ void __launch_bounds__(256, 1)
conv_mma_kernel(const __half* __restrict__ h,
                const int*    __restrict__ nbr_idx,
                const int*    __restrict__ nbr_mask,
                const __half* __restrict__ wt,
                const float*  __restrict__ bias,
                const float*  __restrict__ residual,
                void*         __restrict__ outv,
                float*        __restrict__ stats_part)
{
    extern __shared__ char dsm[];
    __shared__ int   s_idx[CTA_M * KK];
    __shared__ float s_bias[C];
    __shared__ float s_st[256];

    const int tid  = threadIdx.x;
    const int warp = tid >> 5;
    const int lane = tid & 31;
    const int m0   = blockIdx.x * CTA_M;

    const uint32_t smA_u = smem_u32(dsm);
    const uint32_t smW_u = smA_u + PIPE * A_BYTES;

    for (int i = tid; i < CTA_M * KK; i += 256) {
        int gi = m0 * KK + i;
        s_idx[i] = nbr_mask[gi] ? (int)((uint32_t)(nbr_idx[gi] * C) | 0x80000000u) : 0;
    }
    if (tid < C) s_bias[tid] = bias[tid];
    s_st[tid] = 0.f;
    __syncthreads();

    // warp tiling: 4 M-warps x 2 N-warps, warp tile 64x64
    const int mw = warp & 3;
    const int nw = warp >> 2;
    const int lr = lane >> 2;        // 0..7
    const int lc = lane & 3;         // 0..3
    // ldmatrix lane mapping
    const int gq = lane >> 3;
    const int gl = lane & 7;
    const int rowl = (gq & 1) * 8 + gl;
    const int ghi  = gq >> 1;

    float acc[4][8][4];
    #pragma unroll
    for (int a = 0; a < 4; a++)
        #pragma unroll
        for (int b = 0; b < 8; b++)
            #pragma unroll
            for (int q = 0; q < 4; q++) acc[a][b][q] = 0.f;

    const int wcol = tid & 127;
    const int wjb  = tid >> 7;
    const int swA  = (tid & 7) << 4;

    auto issue = [&](int st, int p) {
        const int k  = st >> 1;
        const int ch = st & 1;
        int v = s_idx[tid * KK + k];
        uint32_t sz = (v < 0) ? 16u : 0u;
        const __half* src = h + (v & 0x7FFFFFFF) + ch * 64;
        uint32_t dstrow = smA_u + p * A_BYTES + tid * A_ROWB;
        #pragma unroll
        for (int j = 0; j < 8; j++)
            cp_async16(dstrow + ((j << 4) ^ swA), src + j * 8, sz);
        const __half* wsrc = wt + ((size_t)(k * 2 + ch) * C + wcol) * 64 + wjb * 32;
        uint32_t wdst = smW_u + p * W_BYTES + wcol * W_STRIDEB + wjb * 64;
        #pragma unroll
        for (int j = 0; j < 4; j++)
            cp_async16(wdst + j * 16, wsrc + j * 8, 16u);
        CP_COMMIT();
    };

    issue(0, 0);
    issue(1, 1);

    for (int st = 0; st < NSTAGE; st++) {
        const int p = st % PIPE;
        if (st + 2 < NSTAGE) { issue(st + 2, (st + 2) % PIPE); CP_WAIT(2); }
        else if (st + 1 < NSTAGE) { CP_WAIT(1); }
        else { CP_WAIT(0); }
        __syncthreads();

        const uint32_t Abase = smA_u + p * A_BYTES;
        const uint32_t Wbase = smW_u + p * W_BYTES +
                               (nw * 64 + lr) * W_STRIDEB + lc * 8;

        #pragma unroll
        for (int s = 0; s < 4; s++) {
            uint32_t af[4][4];
            #pragma unroll
            for (int mf = 0; mf < 4; mf++) {
                int row = mw * 64 + mf * 16 + rowl;
                uint32_t addr = Abase + row * A_ROWB +
                                ((((s << 1) | ghi) ^ (row & 7)) << 4);
                ldmatrix_x4(af[mf], addr);
            }
            #pragma unroll
            for (int nf = 0; nf < 8; nf++) {
                uint32_t b0, b1;
                uint32_t baddr = Wbase + nf * (8 * W_STRIDEB) + s * 32;
                asm volatile("ld.shared.v2.b32 {%0,%1}, [%2];"
                             : "=r"(b0), "=r"(b1) : "r"(baddr));
                #pragma unroll
                for (int mf = 0; mf < 4; mf++)
                    mma_f16(acc[mf][nf], af[mf], b0, b1);
            }
        }
        __syncthreads();
    }

    // ---- epilogue ----
    float st_s[8][2], st_q[8][2];
    #pragma unroll
    for (int nf = 0; nf < 8; nf++) {
        st_s[nf][0] = st_s[nf][1] = 0.f;
        st_q[nf][0] = st_q[nf][1] = 0.f;
    }

    #pragma unroll
    for (int mf = 0; mf < 4; mf++) {
        int row = m0 + mw * 64 + mf * 16 + lr;
        #pragma unroll
        for (int nf = 0; nf < 8; nf++) {
            int col = nw * 64 + nf * 8 + lc * 2;
            float2 v0, v1;
            v0.x = acc[mf][nf][0] + s_bias[col];
            v0.y = acc[mf][nf][1] + s_bias[col + 1];
            v1.x = acc[mf][nf][2] + s_bias[col];
            v1.y = acc[mf][nf][3] + s_bias[col + 1];
            if (!OUT_HALF && residual) {
                float2 r0v = *(const float2*)&residual[(size_t)row * C + col];
                float2 r1v = *(const float2*)&residual[(size_t)(row + 8) * C + col];
                v0.x += r0v.x; v0.y += r0v.y;
                v1.x += r1v.x; v1.y += r1v.y;
            }
            if (stats_part) {
                st_s[nf][0] += v0.x + v1.x;
                st_s[nf][1] += v0.y + v1.y;
                st_q[nf][0] += v0.x * v0.x + v1.x * v1.x;
                st_q[nf][1] += v0.y * v0.y + v1.y * v1.y;
            }
            if (OUT_HALF) {
                __half* oh = (__half*)outv;
                *(__half2*)&oh[(size_t)row * C + col]       = __floats2half2_rn(v0.x, v0.y);
                *(__half2*)&oh[(size_t)(row + 8) * C + col] = __floats2half2_rn(v1.x, v1.y);
            } else {
                float* of = (float*)outv;
                *(float2*)&of[(size_t)row * C + col]       = v0;
                *(float2*)&of[(size_t)(row + 8) * C + col] = v1;
            }
        }
    }

    if (stats_part) {
        #pragma unroll
        for (int nf = 0; nf < 8; nf++) {
            #pragma unroll
            for (int j = 0; j < 2; j++) {
                float s = st_s[nf][j], q = st_q[nf][j];
                #pragma unroll
                for (int m = 4; m <= 16; m <<= 1) {
                    s += __shfl_xor_sync(0xFFFFFFFFu, s, m);
                    q += __shfl_xor_sync(0xFFFFFFFFu, q, m);
                }
                if (lr == 0) {
                    int col = nw * 64 + nf * 8 + lc * 2 + j;
                    atomicAdd(&s_st[col],       s);
                    atomicAdd(&s_st[col + 128], q);
                }
            }
        }
        __syncthreads();
        stats_part[blockIdx.x * 256 + tid] = s_st[tid];
    }
}

// ===================== launch =====================
extern "C" void kernel_launch(void* const* d_in, const int* in_sizes, int n_in,
                              void* d_out, int out_size)
{
    const float* features = (const float*)d_in[0];
    const int*   nbr_idx  = (const int*)  d_in[1];
    const int*   nbr_mask = (const int*)  d_in[2];
    const float* gamma1   = (const float*)d_in[3];
    const float* beta1    = (const float*)d_in[4];
    const float* W1       = (const float*)d_in[5];
    const float* bias1    = (const float*)d_in[6];
    const float* gamma2   = (const float*)d_in[7];
    const float* beta2    = (const float*)d_in[8];
    const float* W2       = (const float*)d_in[9];
    const float* bias2    = (const float*)d_in[10];
    float* out = (float*)d_out;

    __half *h_ptr, *yh_ptr, *wt1_ptr, *wt2_ptr;
    float *part_ptr;
    cudaGetSymbolAddress((void**)&h_ptr,    g_h);
    cudaGetSymbolAddress((void**)&yh_ptr,   g_yh);
    cudaGetSymbolAddress((void**)&wt1_ptr,  g_wt1);
    cudaGetSymbolAddress((void**)&wt2_ptr,  g_wt2);
    cudaGetSymbolAddress((void**)&part_ptr, g_part);

    cudaFuncSetAttribute(conv_mma_kernel<true>,
                         cudaFuncAttributeMaxDynamicSharedMemorySize, DSMEM_TOTAL);
    cudaFuncSetAttribute(conv_mma_kernel<false>,
                         cudaFuncAttributeMaxDynamicSharedMemorySize, DSMEM_TOTAL);

    const int stats_grid = NS / 256;
    const int apply_grid = NS / 256;      // 256 rows per block
    const int packw_grid = (2 * KK * C * C) / 256;

    pack_w_kernel<<<packw_grid, 256>>>(W1, W2);

    // ---- layer 1 ----
    bn_stats_kernel<<<stats_grid, 256>>>((const float4*)features);
    reduce_finalize_kernel<<<128, 128>>>(gamma1, beta1);
    bn_apply_pack_kernel<<<apply_grid, 256>>>((const float4*)features, (uint2*)h_ptr);
    conv_mma_kernel<true><<<NCTA, 256, DSMEM_TOTAL>>>(
        h_ptr, nbr_idx, nbr_mask, wt1_ptr, bias1, nullptr, yh_ptr, part_ptr);

    // ---- layer 2: stats from conv1 epilogue ----
    reduce_finalize_kernel<<<128, 128>>>(gamma2, beta2);
    bn_apply_pack_half_kernel<<<apply_grid, 256>>>((const uint4*)yh_ptr, (uint4*)h_ptr);
    conv_mma_kernel<false><<<NCTA, 256, DSMEM_TOTAL>>>(
        h_ptr, nbr_idx, nbr_mask, wt2_ptr, bias2, features, out, nullptr);
}

// round 13
// speedup vs baseline: 1.0295x; 1.0090x over previous
#include <cuda_runtime.h>
#include <cuda_fp16.h>
#include <cstdint>

#define NS   262144
#define C    128
#define KK   27
#define EPSF 1e-4f

#define CTA_M    256
#define PIPE     3
#define NSTAGE   (KK * 2)            // 54 stages: k x 2 cin-chunks of 64
#define A_ROWB   128                 // bytes per A row (64 halves), XOR-swizzled
#define A_BYTES  (CTA_M * A_ROWB)    // 32768
#define W_STRIDEB 160                // bytes per W col (64 halves + pad)
#define W_BYTES  (C * W_STRIDEB)     // 20480
#define DSMEM_TOTAL (PIPE * (A_BYTES + W_BYTES))   // 159744
#define NCTA     (NS / CTA_M)        // 1024

#define STATS_BLKS 2048              // bn_stats blocks (128 rows each)
#define PACKW_BLKS ((2 * KK * C * C) / 256)   // 3456

// ===================== scratch (device globals) =====================
__device__ __half g_h[NS * C];        // BN-ReLU output fp16 (conv gather source)
__device__ __half g_yh[NS * C];       // conv1 output, raw fp16
__device__ __half g_wt1[KK * C * C];  // W permuted to B-fragment layout
__device__ __half g_wt2[KK * C * C];
__device__ float  g_part[STATS_BLKS * 256]; // BN partials [blk][sum(128),sumsq(128)]
__device__ float  g_scale[C];
__device__ float  g_shift[C];

// ===================== helpers =====================
__device__ __forceinline__ uint32_t smem_u32(const void* p) {
    uint32_t a;
    asm("{ .reg .u64 t; cvta.to.shared.u64 t, %1; cvt.u32.u64 %0, t; }"
        : "=r"(a) : "l"(p));
    return a;
}

__device__ __forceinline__ void cp_async16(uint32_t dst, const void* src, uint32_t sz) {
    asm volatile("cp.async.cg.shared.global [%0], [%1], 16, %2;"
                 :: "r"(dst), "l"(src), "r"(sz) : "memory");
}
#define CP_COMMIT() asm volatile("cp.async.commit_group;" ::: "memory")
#define CP_WAIT(n)  asm volatile("cp.async.wait_group %0;" :: "n"(n) : "memory")

__device__ __forceinline__ void ldmatrix_x4(uint32_t* r, uint32_t addr) {
    asm volatile("ldmatrix.sync.aligned.m8n8.x4.shared.b16 {%0,%1,%2,%3}, [%4];"
                 : "=r"(r[0]), "=r"(r[1]), "=r"(r[2]), "=r"(r[3]) : "r"(addr));
}

__device__ __forceinline__ void mma_f16(float* c, const uint32_t* a,
                                        uint32_t b0, uint32_t b1) {
    asm volatile(
        "mma.sync.aligned.m16n8k16.row.col.f32.f16.f16.f32 "
        "{%0,%1,%2,%3}, {%4,%5,%6,%7}, {%8,%9}, {%0,%1,%2,%3};"
        : "+f"(c[0]), "+f"(c[1]), "+f"(c[2]), "+f"(c[3])
        : "r"(a[0]), "r"(a[1]), "r"(a[2]), "r"(a[3]), "r"(b0), "r"(b1));
}

// ===================== BN / prep kernels =====================
// Fused first launch: blocks [0, STATS_BLKS) do bn_stats over 128 rows each;
// blocks [STATS_BLKS, +PACKW_BLKS) do the W permute-pack. Runs concurrently.
__global__ void stats_packw_kernel(const float4* __restrict__ x,
                                   const float* __restrict__ W1,
                                   const float* __restrict__ W2) {
    const int tid = threadIdx.x;
    if (blockIdx.x < STATS_BLKS) {
        __shared__ float4 sh_s[256], sh_q[256];
        const int c4 = tid & 31;
        const int ro = tid >> 5;
        const size_t base = (size_t)blockIdx.x * 128;
        float4 s = make_float4(0.f, 0.f, 0.f, 0.f);
        float4 q = make_float4(0.f, 0.f, 0.f, 0.f);
        #pragma unroll 8
        for (int j = 0; j < 16; j++) {
            float4 v = x[(base + ro + j * 8) * 32 + c4];
            s.x += v.x; s.y += v.y; s.z += v.z; s.w += v.w;
            q.x += v.x * v.x; q.y += v.y * v.y; q.z += v.z * v.z; q.w += v.w * v.w;
        }
        sh_s[tid] = s; sh_q[tid] = q;
        __syncthreads();
        if (tid < C) {
            float ss = 0.f, qq = 0.f;
            const float* ps = (const float*)sh_s;
            const float* pq = (const float*)sh_q;
            #pragma unroll
            for (int r = 0; r < 8; r++) {
                ss += ps[r * 128 + tid];
                qq += pq[r * 128 + tid];
            }
            g_part[blockIdx.x * 256 + tid]       = ss;
            g_part[blockIdx.x * 256 + 128 + tid] = qq;
        }
    } else {
        int g = (blockIdx.x - STATS_BLKS) * 256 + tid;   // 2*KK*C*C
        const float* W = (g < KK * C * C) ? W1 : W2;
        __half* wt     = (g < KK * C * C) ? g_wt1 : g_wt2;
        int o = (g < KK * C * C) ? g : g - KK * C * C;
        int pos = o & 63;
        int col = (o >> 6) & 127;
        int kc  = o >> 13;
        int ch  = kc & 1;
        int k   = kc >> 1;
        int s = pos >> 4, q = pos & 15;
        int c = q >> 2,  d = q & 3;
        int krel = (d < 2) ? (2 * c + d) : (8 + 2 * c + (d - 2));
        int cin = ch * 64 + s * 16 + krel;
        wt[o] = __float2half_rn(W[(k * C + cin) * C + col]);
    }
}

// reduce partials + compute scale/shift, one block per channel
__global__ void reduce_finalize_kernel(const float* __restrict__ gamma,
                                       const float* __restrict__ beta,
                                       int npart) {
    const int c = blockIdx.x;        // 0..127
    float s = 0.f, q = 0.f;
    for (int b = threadIdx.x; b < npart; b += 128) {
        s += g_part[b * 256 + c];
        q += g_part[b * 256 + 128 + c];
    }
    __shared__ float sh_s[128], sh_q[128];
    sh_s[threadIdx.x] = s; sh_q[threadIdx.x] = q;
    __syncthreads();
    for (int o = 64; o > 0; o >>= 1) {
        if (threadIdx.x < o) {
            sh_s[threadIdx.x] += sh_s[threadIdx.x + o];
            sh_q[threadIdx.x] += sh_q[threadIdx.x + o];
        }
        __syncthreads();
    }
    if (threadIdx.x == 0) {
        float mu  = sh_s[0] * (1.f / (float)NS);
        float var = sh_q[0] * (1.f / (float)NS) - mu * mu;
        float sc  = gamma[c] * rsqrtf(var + EPSF);
        g_scale[c] = sc;
        g_shift[c] = beta[c] - mu * sc;
    }
}

// BN + ReLU + fp16 pack, fp32 input (layer 1). 128 rows/block, 16/thread.
__global__ void bn_apply_pack_kernel(const float4* __restrict__ x,
                                     uint2* __restrict__ o) {
    const int tid = threadIdx.x;
    const int c4  = tid & 31;              // float4 column
    const int ro  = tid >> 5;              // 0..7
    const size_t base = (size_t)blockIdx.x * 128;
    const float s0 = g_scale[c4 * 4 + 0], s1 = g_scale[c4 * 4 + 1];
    const float s2 = g_scale[c4 * 4 + 2], s3 = g_scale[c4 * 4 + 3];
    const float t0 = g_shift[c4 * 4 + 0], t1 = g_shift[c4 * 4 + 1];
    const float t2 = g_shift[c4 * 4 + 2], t3 = g_shift[c4 * 4 + 3];
    #pragma unroll 8
    for (int j = 0; j < 16; j++) {
        size_t row = base + ro + j * 8;
        float4 v = x[row * 32 + c4];
        float r0 = fmaxf(fmaf(v.x, s0, t0), 0.f);
        float r1 = fmaxf(fmaf(v.y, s1, t1), 0.f);
        float r2 = fmaxf(fmaf(v.z, s2, t2), 0.f);
        float r3 = fmaxf(fmaf(v.w, s3, t3), 0.f);
        __half2 h0 = __floats2half2_rn(r0, r1);
        __half2 h1 = __floats2half2_rn(r2, r3);
        uint2 w;
        w.x = *reinterpret_cast<uint32_t*>(&h0);
        w.y = *reinterpret_cast<uint32_t*>(&h1);
        o[row * 32 + c4] = w;
    }
}

// BN + ReLU + fp16 pack, fp16 input (layer 2). 128 rows/block, 8/thread.
__global__ void bn_apply_pack_half_kernel(const uint4* __restrict__ x,
                                          uint4* __restrict__ o) {
    const int tid = threadIdx.x;
    const int c8  = tid & 15;              // uint4 column (8 halves)
    const int ro  = tid >> 4;              // 0..15
    const size_t base = (size_t)blockIdx.x * 128;
    float sc[8], sf[8];
    #pragma unroll
    for (int j = 0; j < 8; j++) {
        sc[j] = g_scale[c8 * 8 + j];
        sf[j] = g_shift[c8 * 8 + j];
    }
    #pragma unroll 8
    for (int j = 0; j < 8; j++) {
        size_t row = base + ro + j * 16;
        uint4 v = x[row * 16 + c8];
        uint4 r;
        const __half2* hv = (const __half2*)&v;
        __half2* hr = (__half2*)&r;
        #pragma unroll
        for (int p = 0; p < 4; p++) {
            float2 f = __half22float2(hv[p]);
            float a = fmaxf(fmaf(f.x, sc[p * 2],     sf[p * 2]),     0.f);
            float b = fmaxf(fmaf(f.y, sc[p * 2 + 1], sf[p * 2 + 1]), 0.f);
            hr[p] = __floats2half2_rn(a, b);
        }
        o[row * 16 + c8] = r;
    }
}

// ===================== fp16 mma.sync gather-GEMM conv =====================
// OUT_HALF: write raw fp16 output (conv1); else fp32 (+residual)
template<bool OUT_HALF>
__global__ void __launch_bounds__(256, 1)
conv_mma_kernel(const __half* __restrict__ h,
                const int*    __restrict__ nbr_idx,
                const int*    __restrict__ nbr_mask,
                const __half* __restrict__ wt,
                const float*  __restrict__ bias,
                const float*  __restrict__ residual,
                void*         __restrict__ outv,
                float*        __restrict__ stats_part)
{
    extern __shared__ char dsm[];
    __shared__ int   s_idx[CTA_M * KK];
    __shared__ float s_bias[C];
    __shared__ float s_st[256];

    const int tid  = threadIdx.x;
    const int warp = tid >> 5;
    const int lane = tid & 31;
    const int m0   = blockIdx.x * CTA_M;

    const uint32_t smA_u = smem_u32(dsm);
    const uint32_t smW_u = smA_u + PIPE * A_BYTES;

    for (int i = tid; i < CTA_M * KK; i += 256) {
        int gi = m0 * KK + i;
        s_idx[i] = nbr_mask[gi] ? (int)((uint32_t)(nbr_idx[gi] * C) | 0x80000000u) : 0;
    }
    if (tid < C) s_bias[tid] = bias[tid];
    s_st[tid] = 0.f;
    __syncthreads();

    // warp tiling: 4 M-warps x 2 N-warps, warp tile 64x64
    const int mw = warp & 3;
    const int nw = warp >> 2;
    const int lr = lane >> 2;        // 0..7
    const int lc = lane & 3;         // 0..3
    // ldmatrix lane mapping
    const int gq = lane >> 3;
    const int gl = lane & 7;
    const int rowl = (gq & 1) * 8 + gl;
    const int ghi  = gq >> 1;

    float acc[4][8][4];
    #pragma unroll
    for (int a = 0; a < 4; a++)
        #pragma unroll
        for (int b = 0; b < 8; b++)
            #pragma unroll
            for (int q = 0; q < 4; q++) acc[a][b][q] = 0.f;

    const int wcol = tid & 127;
    const int wjb  = tid >> 7;
    const int swA  = (tid & 7) << 4;

    auto issue = [&](int st, int p) {
        const int k  = st >> 1;
        const int ch = st & 1;
        int v = s_idx[tid * KK + k];
        uint32_t sz = (v < 0) ? 16u : 0u;
        const __half* src = h + (v & 0x7FFFFFFF) + ch * 64;
        uint32_t dstrow = smA_u + p * A_BYTES + tid * A_ROWB;
        #pragma unroll
        for (int j = 0; j < 8; j++)
            cp_async16(dstrow + ((j << 4) ^ swA), src + j * 8, sz);
        const __half* wsrc = wt + ((size_t)(k * 2 + ch) * C + wcol) * 64 + wjb * 32;
        uint32_t wdst = smW_u + p * W_BYTES + wcol * W_STRIDEB + wjb * 64;
        #pragma unroll
        for (int j = 0; j < 4; j++)
            cp_async16(wdst + j * 16, wsrc + j * 8, 16u);
        CP_COMMIT();
    };

    issue(0, 0);
    issue(1, 1);

    for (int st = 0; st < NSTAGE; st++) {
        const int p = st % PIPE;
        if (st + 2 < NSTAGE) { issue(st + 2, (st + 2) % PIPE); CP_WAIT(2); }
        else if (st + 1 < NSTAGE) { CP_WAIT(1); }
        else { CP_WAIT(0); }
        __syncthreads();

        const uint32_t Abase = smA_u + p * A_BYTES;
        const uint32_t Wbase = smW_u + p * W_BYTES +
                               (nw * 64 + lr) * W_STRIDEB + lc * 8;

        #pragma unroll
        for (int s = 0; s < 4; s++) {
            uint32_t af[4][4];
            #pragma unroll
            for (int mf = 0; mf < 4; mf++) {
                int row = mw * 64 + mf * 16 + rowl;
                uint32_t addr = Abase + row * A_ROWB +
                                ((((s << 1) | ghi) ^ (row & 7)) << 4);
                ldmatrix_x4(af[mf], addr);
            }
            #pragma unroll
            for (int nf = 0; nf < 8; nf++) {
                uint32_t b0, b1;
                uint32_t baddr = Wbase + nf * (8 * W_STRIDEB) + s * 32;
                asm volatile("ld.shared.v2.b32 {%0,%1}, [%2];"
                             : "=r"(b0), "=r"(b1) : "r"(baddr));
                #pragma unroll
                for (int mf = 0; mf < 4; mf++)
                    mma_f16(acc[mf][nf], af[mf], b0, b1);
            }
        }
        __syncthreads();
    }

    // ---- epilogue ----
    float st_s[8][2], st_q[8][2];
    #pragma unroll
    for (int nf = 0; nf < 8; nf++) {
        st_s[nf][0] = st_s[nf][1] = 0.f;
        st_q[nf][0] = st_q[nf][1] = 0.f;
    }

    #pragma unroll
    for (int mf = 0; mf < 4; mf++) {
        int row = m0 + mw * 64 + mf * 16 + lr;
        #pragma unroll
        for (int nf = 0; nf < 8; nf++) {
            int col = nw * 64 + nf * 8 + lc * 2;
            float2 v0, v1;
            v0.x = acc[mf][nf][0] + s_bias[col];
            v0.y = acc[mf][nf][1] + s_bias[col + 1];
            v1.x = acc[mf][nf][2] + s_bias[col];
            v1.y = acc[mf][nf][3] + s_bias[col + 1];
            if (!OUT_HALF && residual) {
                float2 r0v = *(const float2*)&residual[(size_t)row * C + col];
                float2 r1v = *(const float2*)&residual[(size_t)(row + 8) * C + col];
                v0.x += r0v.x; v0.y += r0v.y;
                v1.x += r1v.x; v1.y += r1v.y;
            }
            if (stats_part) {
                st_s[nf][0] += v0.x + v1.x;
                st_s[nf][1] += v0.y + v1.y;
                st_q[nf][0] += v0.x * v0.x + v1.x * v1.x;
                st_q[nf][1] += v0.y * v0.y + v1.y * v1.y;
            }
            if (OUT_HALF) {
                __half* oh = (__half*)outv;
                *(__half2*)&oh[(size_t)row * C + col]       = __floats2half2_rn(v0.x, v0.y);
                *(__half2*)&oh[(size_t)(row + 8) * C + col] = __floats2half2_rn(v1.x, v1.y);
            } else {
                float* of = (float*)outv;
                *(float2*)&of[(size_t)row * C + col]       = v0;
                *(float2*)&of[(size_t)(row + 8) * C + col] = v1;
            }
        }
    }

    if (stats_part) {
        #pragma unroll
        for (int nf = 0; nf < 8; nf++) {
            #pragma unroll
            for (int j = 0; j < 2; j++) {
                float s = st_s[nf][j], q = st_q[nf][j];
                #pragma unroll
                for (int m = 4; m <= 16; m <<= 1) {
                    s += __shfl_xor_sync(0xFFFFFFFFu, s, m);
                    q += __shfl_xor_sync(0xFFFFFFFFu, q, m);
                }
                if (lr == 0) {
                    int col = nw * 64 + nf * 8 + lc * 2 + j;
                    atomicAdd(&s_st[col],       s);
                    atomicAdd(&s_st[col + 128], q);
                }
            }
        }
        __syncthreads();
        stats_part[blockIdx.x * 256 + tid] = s_st[tid];
    }
}

// ===================== launch =====================
extern "C" void kernel_launch(void* const* d_in, const int* in_sizes, int n_in,
                              void* d_out, int out_size)
{
    const float* features = (const float*)d_in[0];
    const int*   nbr_idx  = (const int*)  d_in[1];
    const int*   nbr_mask = (const int*)  d_in[2];
    const float* gamma1   = (const float*)d_in[3];
    const float* beta1    = (const float*)d_in[4];
    const float* W1       = (const float*)d_in[5];
    const float* bias1    = (const float*)d_in[6];
    const float* gamma2   = (const float*)d_in[7];
    const float* beta2    = (const float*)d_in[8];
    const float* W2       = (const float*)d_in[9];
    const float* bias2    = (const float*)d_in[10];
    float* out = (float*)d_out;

    __half *h_ptr, *yh_ptr, *wt1_ptr, *wt2_ptr;
    float *part_ptr;
    cudaGetSymbolAddress((void**)&h_ptr,    g_h);
    cudaGetSymbolAddress((void**)&yh_ptr,   g_yh);
    cudaGetSymbolAddress((void**)&wt1_ptr,  g_wt1);
    cudaGetSymbolAddress((void**)&wt2_ptr,  g_wt2);
    cudaGetSymbolAddress((void**)&part_ptr, g_part);

    cudaFuncSetAttribute(conv_mma_kernel<true>,
                         cudaFuncAttributeMaxDynamicSharedMemorySize, DSMEM_TOTAL);
    cudaFuncSetAttribute(conv_mma_kernel<false>,
                         cudaFuncAttributeMaxDynamicSharedMemorySize, DSMEM_TOTAL);

    const int apply_grid = NS / 128;      // 2048 blocks

    // ---- layer 1 (stats + weight pack fused in one concurrent launch) ----
    stats_packw_kernel<<<STATS_BLKS + PACKW_BLKS, 256>>>(
        (const float4*)features, W1, W2);
    reduce_finalize_kernel<<<128, 128>>>(gamma1, beta1, STATS_BLKS);
    bn_apply_pack_kernel<<<apply_grid, 256>>>((const float4*)features, (uint2*)h_ptr);
    conv_mma_kernel<true><<<NCTA, 256, DSMEM_TOTAL>>>(
        h_ptr, nbr_idx, nbr_mask, wt1_ptr, bias1, nullptr, yh_ptr, part_ptr);

    // ---- layer 2: stats from conv1 epilogue ----
    reduce_finalize_kernel<<<128, 128>>>(gamma2, beta2, NCTA);
    bn_apply_pack_half_kernel<<<apply_grid, 256>>>((const uint4*)yh_ptr, (uint4*)h_ptr);
    conv_mma_kernel<false><<<NCTA, 256, DSMEM_TOTAL>>>(
        h_ptr, nbr_idx, nbr_mask, wt2_ptr, bias2, features, out, nullptr);
}

// round 14
// speedup vs baseline: 1.0783x; 1.0475x over previous
#include <cuda_runtime.h>
#include <cuda_fp16.h>
#include <cstdint>

#define NS   262144
#define C    128
#define KK   27
#define EPSF 1e-4f

#define CTA_M    256
#define NTHREADS 512
#define PIPE     3
#define NSTAGE   (KK * 2)            // 54 stages: k x 2 cin-chunks of 64
#define A_ROWB   128                 // bytes per A row (64 halves), XOR-swizzled
#define A_BYTES  (CTA_M * A_ROWB)    // 32768
#define W_STRIDEB 160                // bytes per W col (64 halves + pad)
#define W_BYTES  (C * W_STRIDEB)     // 20480
#define DSMEM_TOTAL (PIPE * (A_BYTES + W_BYTES))   // 159744
#define NCTA     (NS / CTA_M)        // 1024

#define STATS_BLKS 2048              // bn_stats blocks (128 rows each)
#define PACKW_BLKS ((2 * KK * C * C) / 256)   // 3456

// ===================== scratch (device globals) =====================
__device__ __half g_h[NS * C];        // BN-ReLU output fp16 (conv gather source)
__device__ __half g_yh[NS * C];       // conv1 output, raw fp16
__device__ __half g_wt1[KK * C * C];  // W permuted to B-fragment layout
__device__ __half g_wt2[KK * C * C];
__device__ float  g_part[STATS_BLKS * 256]; // BN partials [blk][sum(128),sumsq(128)]
__device__ float  g_scale[C];
__device__ float  g_shift[C];

// ===================== helpers =====================
__device__ __forceinline__ uint32_t smem_u32(const void* p) {
    uint32_t a;
    asm("{ .reg .u64 t; cvta.to.shared.u64 t, %1; cvt.u32.u64 %0, t; }"
        : "=r"(a) : "l"(p));
    return a;
}

__device__ __forceinline__ void cp_async16(uint32_t dst, const void* src, uint32_t sz) {
    asm volatile("cp.async.cg.shared.global [%0], [%1], 16, %2;"
                 :: "r"(dst), "l"(src), "r"(sz) : "memory");
}
#define CP_COMMIT() asm volatile("cp.async.commit_group;" ::: "memory")
#define CP_WAIT(n)  asm volatile("cp.async.wait_group %0;" :: "n"(n) : "memory")

__device__ __forceinline__ void ldmatrix_x4(uint32_t* r, uint32_t addr) {
    asm volatile("ldmatrix.sync.aligned.m8n8.x4.shared.b16 {%0,%1,%2,%3}, [%4];"
                 : "=r"(r[0]), "=r"(r[1]), "=r"(r[2]), "=r"(r[3]) : "r"(addr));
}

__device__ __forceinline__ void mma_f16(float* c, const uint32_t* a,
                                        uint32_t b0, uint32_t b1) {
    asm volatile(
        "mma.sync.aligned.m16n8k16.row.col.f32.f16.f16.f32 "
        "{%0,%1,%2,%3}, {%4,%5,%6,%7}, {%8,%9}, {%0,%1,%2,%3};"
        : "+f"(c[0]), "+f"(c[1]), "+f"(c[2]), "+f"(c[3])
        : "r"(a[0]), "r"(a[1]), "r"(a[2]), "r"(a[3]), "r"(b0), "r"(b1));
}

// ===================== BN / prep kernels =====================
// Fused first launch: stats blocks + W permute-pack blocks, concurrent.
__global__ void stats_packw_kernel(const float4* __restrict__ x,
                                   const float* __restrict__ W1,
                                   const float* __restrict__ W2) {
    const int tid = threadIdx.x;
    if (blockIdx.x < STATS_BLKS) {
        __shared__ float4 sh_s[256], sh_q[256];
        const int c4 = tid & 31;
        const int ro = tid >> 5;
        const size_t base = (size_t)blockIdx.x * 128;
        float4 s = make_float4(0.f, 0.f, 0.f, 0.f);
        float4 q = make_float4(0.f, 0.f, 0.f, 0.f);
        #pragma unroll 8
        for (int j = 0; j < 16; j++) {
            float4 v = x[(base + ro + j * 8) * 32 + c4];
            s.x += v.x; s.y += v.y; s.z += v.z; s.w += v.w;
            q.x += v.x * v.x; q.y += v.y * v.y; q.z += v.z * v.z; q.w += v.w * v.w;
        }
        sh_s[tid] = s; sh_q[tid] = q;
        __syncthreads();
        if (tid < C) {
            float ss = 0.f, qq = 0.f;
            const float* ps = (const float*)sh_s;
            const float* pq = (const float*)sh_q;
            #pragma unroll
            for (int r = 0; r < 8; r++) {
                ss += ps[r * 128 + tid];
                qq += pq[r * 128 + tid];
            }
            g_part[blockIdx.x * 256 + tid]       = ss;
            g_part[blockIdx.x * 256 + 128 + tid] = qq;
        }
    } else {
        int g = (blockIdx.x - STATS_BLKS) * 256 + tid;   // 2*KK*C*C
        const float* W = (g < KK * C * C) ? W1 : W2;
        __half* wt     = (g < KK * C * C) ? g_wt1 : g_wt2;
        int o = (g < KK * C * C) ? g : g - KK * C * C;
        int pos = o & 63;
        int col = (o >> 6) & 127;
        int kc  = o >> 13;
        int ch  = kc & 1;
        int k   = kc >> 1;
        int s = pos >> 4, q = pos & 15;
        int c = q >> 2,  d = q & 3;
        int krel = (d < 2) ? (2 * c + d) : (8 + 2 * c + (d - 2));
        int cin = ch * 64 + s * 16 + krel;
        wt[o] = __float2half_rn(W[(k * C + cin) * C + col]);
    }
}

// reduce partials + compute scale/shift, one block per channel
__global__ void reduce_finalize_kernel(const float* __restrict__ gamma,
                                       const float* __restrict__ beta,
                                       int npart) {
    const int c = blockIdx.x;        // 0..127
    float s = 0.f, q = 0.f;
    for (int b = threadIdx.x; b < npart; b += 128) {
        s += g_part[b * 256 + c];
        q += g_part[b * 256 + 128 + c];
    }
    __shared__ float sh_s[128], sh_q[128];
    sh_s[threadIdx.x] = s; sh_q[threadIdx.x] = q;
    __syncthreads();
    for (int o = 64; o > 0; o >>= 1) {
        if (threadIdx.x < o) {
            sh_s[threadIdx.x] += sh_s[threadIdx.x + o];
            sh_q[threadIdx.x] += sh_q[threadIdx.x + o];
        }
        __syncthreads();
    }
    if (threadIdx.x == 0) {
        float mu  = sh_s[0] * (1.f / (float)NS);
        float var = sh_q[0] * (1.f / (float)NS) - mu * mu;
        float sc  = gamma[c] * rsqrtf(var + EPSF);
        g_scale[c] = sc;
        g_shift[c] = beta[c] - mu * sc;
    }
}

// BN + ReLU + fp16 pack, fp32 input (layer 1). 128 rows/block, 16/thread.
__global__ void bn_apply_pack_kernel(const float4* __restrict__ x,
                                     uint2* __restrict__ o) {
    const int tid = threadIdx.x;
    const int c4  = tid & 31;              // float4 column
    const int ro  = tid >> 5;              // 0..7
    const size_t base = (size_t)blockIdx.x * 128;
    const float s0 = g_scale[c4 * 4 + 0], s1 = g_scale[c4 * 4 + 1];
    const float s2 = g_scale[c4 * 4 + 2], s3 = g_scale[c4 * 4 + 3];
    const float t0 = g_shift[c4 * 4 + 0], t1 = g_shift[c4 * 4 + 1];
    const float t2 = g_shift[c4 * 4 + 2], t3 = g_shift[c4 * 4 + 3];
    #pragma unroll 8
    for (int j = 0; j < 16; j++) {
        size_t row = base + ro + j * 8;
        float4 v = x[row * 32 + c4];
        float r0 = fmaxf(fmaf(v.x, s0, t0), 0.f);
        float r1 = fmaxf(fmaf(v.y, s1, t1), 0.f);
        float r2 = fmaxf(fmaf(v.z, s2, t2), 0.f);
        float r3 = fmaxf(fmaf(v.w, s3, t3), 0.f);
        __half2 h0 = __floats2half2_rn(r0, r1);
        __half2 h1 = __floats2half2_rn(r2, r3);
        uint2 w;
        w.x = *reinterpret_cast<uint32_t*>(&h0);
        w.y = *reinterpret_cast<uint32_t*>(&h1);
        o[row * 32 + c4] = w;
    }
}

// BN + ReLU + fp16 pack, fp16 input (layer 2). 128 rows/block, 8/thread.
__global__ void bn_apply_pack_half_kernel(const uint4* __restrict__ x,
                                          uint4* __restrict__ o) {
    const int tid = threadIdx.x;
    const int c8  = tid & 15;              // uint4 column (8 halves)
    const int ro  = tid >> 4;              // 0..15
    const size_t base = (size_t)blockIdx.x * 128;
    float sc[8], sf[8];
    #pragma unroll
    for (int j = 0; j < 8; j++) {
        sc[j] = g_scale[c8 * 8 + j];
        sf[j] = g_shift[c8 * 8 + j];
    }
    #pragma unroll 8
    for (int j = 0; j < 8; j++) {
        size_t row = base + ro + j * 16;
        uint4 v = x[row * 16 + c8];
        uint4 r;
        const __half2* hv = (const __half2*)&v;
        __half2* hr = (__half2*)&r;
        #pragma unroll
        for (int p = 0; p < 4; p++) {
            float2 f = __half22float2(hv[p]);
            float a = fmaxf(fmaf(f.x, sc[p * 2],     sf[p * 2]),     0.f);
            float b = fmaxf(fmaf(f.y, sc[p * 2 + 1], sf[p * 2 + 1]), 0.f);
            hr[p] = __floats2half2_rn(a, b);
        }
        o[row * 16 + c8] = r;
    }
}

// ===================== fp16 mma.sync gather-GEMM conv =====================
// 512 threads / 16 warps, CTA tile 256x128, warp tile 64x32 (4M x 4N warps).
// OUT_HALF: write raw fp16 output (conv1); else fp32 (+residual)
template<bool OUT_HALF>
__global__ void __launch_bounds__(NTHREADS, 1)
conv_mma_kernel(const __half* __restrict__ h,
                const int*    __restrict__ nbr_idx,
                const int*    __restrict__ nbr_mask,
                const __half* __restrict__ wt,
                const float*  __restrict__ bias,
                const float*  __restrict__ residual,
                void*         __restrict__ outv,
                float*        __restrict__ stats_part)
{
    extern __shared__ char dsm[];
    __shared__ int   s_idx[CTA_M * KK];
    __shared__ float s_bias[C];
    __shared__ float s_st[256];

    const int tid  = threadIdx.x;
    const int warp = tid >> 5;            // 0..15
    const int lane = tid & 31;
    const int m0   = blockIdx.x * CTA_M;

    const uint32_t smA_u = smem_u32(dsm);
    const uint32_t smW_u = smA_u + PIPE * A_BYTES;

    for (int i = tid; i < CTA_M * KK; i += NTHREADS) {
        int gi = m0 * KK + i;
        s_idx[i] = nbr_mask[gi] ? (int)((uint32_t)(nbr_idx[gi] * C) | 0x80000000u) : 0;
    }
    if (tid < C) s_bias[tid] = bias[tid];
    if (tid < 256) s_st[tid] = 0.f;
    __syncthreads();

    // warp tiling: 4 M-warps x 4 N-warps, warp tile 64x32
    const int mw = warp & 3;
    const int nw = warp >> 2;             // 0..3
    const int lr = lane >> 2;             // 0..7
    const int lc = lane & 3;              // 0..3
    // ldmatrix lane mapping
    const int gq = lane >> 3;
    const int gl = lane & 7;
    const int rowl = (gq & 1) * 8 + gl;
    const int ghi  = gq >> 1;

    float acc[4][4][4];
    #pragma unroll
    for (int a = 0; a < 4; a++)
        #pragma unroll
        for (int b = 0; b < 4; b++)
            #pragma unroll
            for (int q = 0; q < 4; q++) acc[a][b][q] = 0.f;

    // gather/copy split across 512 threads
    const int arow  = tid >> 1;            // A row 0..255
    const int ahalf = tid & 1;             // which 64B half of the row
    const int swAr  = (arow & 7) << 4;     // XOR swizzle term
    const int wcol  = tid & 127;
    const int wq    = tid >> 7;            // 0..3 : 32B quarter of W col

    auto issue = [&](int st, int p) {
        const int k  = st >> 1;
        const int ch = st & 1;
        int v = s_idx[arow * KK + k];
        uint32_t sz = (v < 0) ? 16u : 0u;
        const __half* src = h + (v & 0x7FFFFFFF) + ch * 64 + ahalf * 32;
        uint32_t dstrow = smA_u + p * A_BYTES + arow * A_ROWB;
        #pragma unroll
        for (int j = 0; j < 4; j++)
            cp_async16(dstrow + ((((ahalf << 2) + j) << 4) ^ swAr), src + j * 8, sz);
        const __half* wsrc = wt + ((size_t)(k * 2 + ch) * C + wcol) * 64 + wq * 16;
        uint32_t wdst = smW_u + p * W_BYTES + wcol * W_STRIDEB + wq * 32;
        cp_async16(wdst,      wsrc,     16u);
        cp_async16(wdst + 16, wsrc + 8, 16u);
        CP_COMMIT();
    };

    issue(0, 0);
    issue(1, 1);

    for (int st = 0; st < NSTAGE; st++) {
        const int p = st % PIPE;
        if (st + 2 < NSTAGE) { issue(st + 2, (st + 2) % PIPE); CP_WAIT(2); }
        else if (st + 1 < NSTAGE) { CP_WAIT(1); }
        else { CP_WAIT(0); }
        __syncthreads();

        const uint32_t Abase = smA_u + p * A_BYTES;
        const uint32_t Wbase = smW_u + p * W_BYTES +
                               (nw * 32 + lr) * W_STRIDEB + lc * 8;

        #pragma unroll
        for (int s = 0; s < 4; s++) {
            uint32_t af[4][4];
            #pragma unroll
            for (int mf = 0; mf < 4; mf++) {
                int row = mw * 64 + mf * 16 + rowl;
                uint32_t addr = Abase + row * A_ROWB +
                                ((((s << 1) | ghi) ^ (row & 7)) << 4);
                ldmatrix_x4(af[mf], addr);
            }
            #pragma unroll
            for (int nf = 0; nf < 4; nf++) {
                uint32_t b0, b1;
                uint32_t baddr = Wbase + nf * (8 * W_STRIDEB) + s * 32;
                asm volatile("ld.shared.v2.b32 {%0,%1}, [%2];"
                             : "=r"(b0), "=r"(b1) : "r"(baddr));
                #pragma unroll
                for (int mf = 0; mf < 4; mf++)
                    mma_f16(acc[mf][nf], af[mf], b0, b1);
            }
        }
        __syncthreads();
    }

    // ---- epilogue ----
    float st_s[4][2], st_q[4][2];
    #pragma unroll
    for (int nf = 0; nf < 4; nf++) {
        st_s[nf][0] = st_s[nf][1] = 0.f;
        st_q[nf][0] = st_q[nf][1] = 0.f;
    }

    #pragma unroll
    for (int mf = 0; mf < 4; mf++) {
        int row = m0 + mw * 64 + mf * 16 + lr;
        #pragma unroll
        for (int nf = 0; nf < 4; nf++) {
            int col = nw * 32 + nf * 8 + lc * 2;
            float2 v0, v1;
            v0.x = acc[mf][nf][0] + s_bias[col];
            v0.y = acc[mf][nf][1] + s_bias[col + 1];
            v1.x = acc[mf][nf][2] + s_bias[col];
            v1.y = acc[mf][nf][3] + s_bias[col + 1];
            if (!OUT_HALF && residual) {
                float2 r0v = *(const float2*)&residual[(size_t)row * C + col];
                float2 r1v = *(const float2*)&residual[(size_t)(row + 8) * C + col];
                v0.x += r0v.x; v0.y += r0v.y;
                v1.x += r1v.x; v1.y += r1v.y;
            }
            if (stats_part) {
                st_s[nf][0] += v0.x + v1.x;
                st_s[nf][1] += v0.y + v1.y;
                st_q[nf][0] += v0.x * v0.x + v1.x * v1.x;
                st_q[nf][1] += v0.y * v0.y + v1.y * v1.y;
            }
            if (OUT_HALF) {
                __half* oh = (__half*)outv;
                *(__half2*)&oh[(size_t)row * C + col]       = __floats2half2_rn(v0.x, v0.y);
                *(__half2*)&oh[(size_t)(row + 8) * C + col] = __floats2half2_rn(v1.x, v1.y);
            } else {
                float* of = (float*)outv;
                *(float2*)&of[(size_t)row * C + col]       = v0;
                *(float2*)&of[(size_t)(row + 8) * C + col] = v1;
            }
        }
    }

    if (stats_part) {
        #pragma unroll
        for (int nf = 0; nf < 4; nf++) {
            #pragma unroll
            for (int j = 0; j < 2; j++) {
                float s = st_s[nf][j], q = st_q[nf][j];
                #pragma unroll
                for (int m = 4; m <= 16; m <<= 1) {
                    s += __shfl_xor_sync(0xFFFFFFFFu, s, m);
                    q += __shfl_xor_sync(0xFFFFFFFFu, q, m);
                }
                if (lr == 0) {
                    int col = nw * 32 + nf * 8 + lc * 2 + j;
                    atomicAdd(&s_st[col],       s);
                    atomicAdd(&s_st[col + 128], q);
                }
            }
        }
        __syncthreads();
        if (tid < 256)
            stats_part[blockIdx.x * 256 + tid] = s_st[tid];
    }
}

// ===================== launch =====================
extern "C" void kernel_launch(void* const* d_in, const int* in_sizes, int n_in,
                              void* d_out, int out_size)
{
    const float* features = (const float*)d_in[0];
    const int*   nbr_idx  = (const int*)  d_in[1];
    const int*   nbr_mask = (const int*)  d_in[2];
    const float* gamma1   = (const float*)d_in[3];
    const float* beta1    = (const float*)d_in[4];
    const float* W1       = (const float*)d_in[5];
    const float* bias1    = (const float*)d_in[6];
    const float* gamma2   = (const float*)d_in[7];
    const float* beta2    = (const float*)d_in[8];
    const float* W2       = (const float*)d_in[9];
    const float* bias2    = (const float*)d_in[10];
    float* out = (float*)d_out;

    __half *h_ptr, *yh_ptr, *wt1_ptr, *wt2_ptr;
    float *part_ptr;
    cudaGetSymbolAddress((void**)&h_ptr,    g_h);
    cudaGetSymbolAddress((void**)&yh_ptr,   g_yh);
    cudaGetSymbolAddress((void**)&wt1_ptr,  g_wt1);
    cudaGetSymbolAddress((void**)&wt2_ptr,  g_wt2);
    cudaGetSymbolAddress((void**)&part_ptr, g_part);

    cudaFuncSetAttribute(conv_mma_kernel<true>,
                         cudaFuncAttributeMaxDynamicSharedMemorySize, DSMEM_TOTAL);
    cudaFuncSetAttribute(conv_mma_kernel<false>,
                         cudaFuncAttributeMaxDynamicSharedMemorySize, DSMEM_TOTAL);

    const int apply_grid = NS / 128;      // 2048 blocks

    // ---- layer 1 (stats + weight pack fused in one concurrent launch) ----
    stats_packw_kernel<<<STATS_BLKS + PACKW_BLKS, 256>>>(
        (const float4*)features, W1, W2);
    reduce_finalize_kernel<<<128, 128>>>(gamma1, beta1, STATS_BLKS);
    bn_apply_pack_kernel<<<apply_grid, 256>>>((const float4*)features, (uint2*)h_ptr);
    conv_mma_kernel<true><<<NCTA, NTHREADS, DSMEM_TOTAL>>>(
        h_ptr, nbr_idx, nbr_mask, wt1_ptr, bias1, nullptr, yh_ptr, part_ptr);

    // ---- layer 2: stats from conv1 epilogue ----
    reduce_finalize_kernel<<<128, 128>>>(gamma2, beta2, NCTA);
    bn_apply_pack_half_kernel<<<apply_grid, 256>>>((const uint4*)yh_ptr, (uint4*)h_ptr);
    conv_mma_kernel<false><<<NCTA, NTHREADS, DSMEM_TOTAL>>>(
        h_ptr, nbr_idx, nbr_mask, wt2_ptr, bias2, features, out, nullptr);
}

// round 15
// speedup vs baseline: 1.2816x; 1.1885x over previous
#include <cuda_runtime.h>
#include <cuda_fp16.h>
#include <cstdint>

#define NS   262144
#define C    128
#define KK   27
#define EPSF 1e-4f

#define CTA_M    256
#define NTHREADS 512
#define PIPE     4
#define NSTAGE   (KK * 2)            // 54 stages: k x 2 cin-chunks of 64
#define A_ROWB   128                 // bytes per A row (64 halves), XOR-swizzled
#define A_BYTES  (CTA_M * A_ROWB)    // 32768
#define W_STRIDEB 160                // bytes per W col (64 halves + pad)
#define W_BYTES  (C * W_STRIDEB)     // 20480
#define DSMEM_TOTAL (PIPE * (A_BYTES + W_BYTES))   // 212992
#define NCTA     (NS / CTA_M)        // 1024

#define STATS_BLKS 2048              // bn_stats blocks (128 rows each)
#define PACKW_BLKS ((2 * KK * C * C) / 256)   // 3456
#define IDX_BLKS   (NS / 128)        // 2048

// ===================== scratch (device globals) =====================
__device__ __half g_h[NS * C];        // BN-ReLU output fp16 (conv gather source)
__device__ __half g_yh[NS * C];       // conv1 output, raw fp16
__device__ __half g_wt1[KK * C * C];  // W permuted to B-fragment layout
__device__ __half g_wt2[KK * C * C];
__device__ int    g_idx[KK * NS];     // transposed rulebook: [k][site]
__device__ float  g_part[STATS_BLKS * 256]; // BN partials [blk][sum(128),sumsq(128)]
__device__ float  g_scale[C];
__device__ float  g_shift[C];

// ===================== helpers =====================
__device__ __forceinline__ uint32_t smem_u32(const void* p) {
    uint32_t a;
    asm("{ .reg .u64 t; cvta.to.shared.u64 t, %1; cvt.u32.u64 %0, t; }"
        : "=r"(a) : "l"(p));
    return a;
}

__device__ __forceinline__ void cp_async16(uint32_t dst, const void* src, uint32_t sz) {
    asm volatile("cp.async.cg.shared.global [%0], [%1], 16, %2;"
                 :: "r"(dst), "l"(src), "r"(sz) : "memory");
}
#define CP_COMMIT() asm volatile("cp.async.commit_group;" ::: "memory")
#define CP_WAIT(n)  asm volatile("cp.async.wait_group %0;" :: "n"(n) : "memory")

__device__ __forceinline__ void ldmatrix_x4(uint32_t* r, uint32_t addr) {
    asm volatile("ldmatrix.sync.aligned.m8n8.x4.shared.b16 {%0,%1,%2,%3}, [%4];"
                 : "=r"(r[0]), "=r"(r[1]), "=r"(r[2]), "=r"(r[3]) : "r"(addr));
}

__device__ __forceinline__ void mma_f16(float* c, const uint32_t* a,
                                        uint32_t b0, uint32_t b1) {
    asm volatile(
        "mma.sync.aligned.m16n8k16.row.col.f32.f16.f16.f32 "
        "{%0,%1,%2,%3}, {%4,%5,%6,%7}, {%8,%9}, {%0,%1,%2,%3};"
        : "+f"(c[0]), "+f"(c[1]), "+f"(c[2]), "+f"(c[3])
        : "r"(a[0]), "r"(a[1]), "r"(a[2]), "r"(a[3]), "r"(b0), "r"(b1));
}

// ===================== BN / prep kernels =====================
// Fused first launch (concurrent block ranges):
//   [0, STATS)              : BN stats partials over 128 rows each
//   [STATS, +PACKW)         : W permute-pack (both tensors)
//   [STATS+PACKW, +IDX)     : rulebook transpose+encode
__global__ void prep_kernel(const float4* __restrict__ x,
                            const float* __restrict__ W1,
                            const float* __restrict__ W2,
                            const int* __restrict__ nbr_idx,
                            const int* __restrict__ nbr_mask) {
    const int tid = threadIdx.x;
    if (blockIdx.x < STATS_BLKS) {
        __shared__ float4 sh_s[256], sh_q[256];
        const int c4 = tid & 31;
        const int ro = tid >> 5;
        const size_t base = (size_t)blockIdx.x * 128;
        float4 s = make_float4(0.f, 0.f, 0.f, 0.f);
        float4 q = make_float4(0.f, 0.f, 0.f, 0.f);
        #pragma unroll 8
        for (int j = 0; j < 16; j++) {
            float4 v = x[(base + ro + j * 8) * 32 + c4];
            s.x += v.x; s.y += v.y; s.z += v.z; s.w += v.w;
            q.x += v.x * v.x; q.y += v.y * v.y; q.z += v.z * v.z; q.w += v.w * v.w;
        }
        sh_s[tid] = s; sh_q[tid] = q;
        __syncthreads();
        if (tid < C) {
            float ss = 0.f, qq = 0.f;
            const float* ps = (const float*)sh_s;
            const float* pq = (const float*)sh_q;
            #pragma unroll
            for (int r = 0; r < 8; r++) {
                ss += ps[r * 128 + tid];
                qq += pq[r * 128 + tid];
            }
            g_part[blockIdx.x * 256 + tid]       = ss;
            g_part[blockIdx.x * 256 + 128 + tid] = qq;
        }
    } else if (blockIdx.x < STATS_BLKS + PACKW_BLKS) {
        int g = (blockIdx.x - STATS_BLKS) * 256 + tid;   // 2*KK*C*C
        const float* W = (g < KK * C * C) ? W1 : W2;
        __half* wt     = (g < KK * C * C) ? g_wt1 : g_wt2;
        int o = (g < KK * C * C) ? g : g - KK * C * C;
        int pos = o & 63;
        int col = (o >> 6) & 127;
        int kc  = o >> 13;
        int ch  = kc & 1;
        int k   = kc >> 1;
        int s = pos >> 4, q = pos & 15;
        int c = q >> 2,  d = q & 3;
        int krel = (d < 2) ? (2 * c + d) : (8 + 2 * c + (d - 2));
        int cin = ch * 64 + s * 16 + krel;
        wt[o] = __float2half_rn(W[(k * C + cin) * C + col]);
    } else {
        __shared__ int sm[128 * KK];
        const int m0 = (blockIdx.x - STATS_BLKS - PACKW_BLKS) * 128;
        for (int i = tid; i < 128 * KK; i += 256) {
            int gi = m0 * KK + i;
            sm[i] = nbr_mask[gi] ? (int)((uint32_t)(nbr_idx[gi] * C) | 0x80000000u) : 0;
        }
        __syncthreads();
        for (int i = tid; i < 128 * KK; i += 256) {
            int k = i >> 7, r = i & 127;
            g_idx[k * NS + m0 + r] = sm[r * KK + k];
        }
    }
}

// reduce partials + compute scale/shift, one block per channel
__global__ void reduce_finalize_kernel(const float* __restrict__ gamma,
                                       const float* __restrict__ beta,
                                       int npart) {
    const int c = blockIdx.x;        // 0..127
    float s = 0.f, q = 0.f;
    for (int b = threadIdx.x; b < npart; b += 128) {
        s += g_part[b * 256 + c];
        q += g_part[b * 256 + 128 + c];
    }
    __shared__ float sh_s[128], sh_q[128];
    sh_s[threadIdx.x] = s; sh_q[threadIdx.x] = q;
    __syncthreads();
    for (int o = 64; o > 0; o >>= 1) {
        if (threadIdx.x < o) {
            sh_s[threadIdx.x] += sh_s[threadIdx.x + o];
            sh_q[threadIdx.x] += sh_q[threadIdx.x + o];
        }
        __syncthreads();
    }
    if (threadIdx.x == 0) {
        float mu  = sh_s[0] * (1.f / (float)NS);
        float var = sh_q[0] * (1.f / (float)NS) - mu * mu;
        float sc  = gamma[c] * rsqrtf(var + EPSF);
        g_scale[c] = sc;
        g_shift[c] = beta[c] - mu * sc;
    }
}

// BN + ReLU + fp16 pack, fp32 input (layer 1). 128 rows/block, 16/thread.
__global__ void bn_apply_pack_kernel(const float4* __restrict__ x,
                                     uint2* __restrict__ o) {
    const int tid = threadIdx.x;
    const int c4  = tid & 31;              // float4 column
    const int ro  = tid >> 5;              // 0..7
    const size_t base = (size_t)blockIdx.x * 128;
    const float s0 = g_scale[c4 * 4 + 0], s1 = g_scale[c4 * 4 + 1];
    const float s2 = g_scale[c4 * 4 + 2], s3 = g_scale[c4 * 4 + 3];
    const float t0 = g_shift[c4 * 4 + 0], t1 = g_shift[c4 * 4 + 1];
    const float t2 = g_shift[c4 * 4 + 2], t3 = g_shift[c4 * 4 + 3];
    #pragma unroll 8
    for (int j = 0; j < 16; j++) {
        size_t row = base + ro + j * 8;
        float4 v = x[row * 32 + c4];
        float r0 = fmaxf(fmaf(v.x, s0, t0), 0.f);
        float r1 = fmaxf(fmaf(v.y, s1, t1), 0.f);
        float r2 = fmaxf(fmaf(v.z, s2, t2), 0.f);
        float r3 = fmaxf(fmaf(v.w, s3, t3), 0.f);
        __half2 h0 = __floats2half2_rn(r0, r1);
        __half2 h1 = __floats2half2_rn(r2, r3);
        uint2 w;
        w.x = *reinterpret_cast<uint32_t*>(&h0);
        w.y = *reinterpret_cast<uint32_t*>(&h1);
        o[row * 32 + c4] = w;
    }
}

// BN + ReLU + fp16 pack, fp16 input (layer 2). 128 rows/block, 8/thread.
__global__ void bn_apply_pack_half_kernel(const uint4* __restrict__ x,
                                          uint4* __restrict__ o) {
    const int tid = threadIdx.x;
    const int c8  = tid & 15;              // uint4 column (8 halves)
    const int ro  = tid >> 4;              // 0..15
    const size_t base = (size_t)blockIdx.x * 128;
    float sc[8], sf[8];
    #pragma unroll
    for (int j = 0; j < 8; j++) {
        sc[j] = g_scale[c8 * 8 + j];
        sf[j] = g_shift[c8 * 8 + j];
    }
    #pragma unroll 8
    for (int j = 0; j < 8; j++) {
        size_t row = base + ro + j * 16;
        uint4 v = x[row * 16 + c8];
        uint4 r;
        const __half2* hv = (const __half2*)&v;
        __half2* hr = (__half2*)&r;
        #pragma unroll
        for (int p = 0; p < 4; p++) {
            float2 f = __half22float2(hv[p]);
            float a = fmaxf(fmaf(f.x, sc[p * 2],     sf[p * 2]),     0.f);
            float b = fmaxf(fmaf(f.y, sc[p * 2 + 1], sf[p * 2 + 1]), 0.f);
            hr[p] = __floats2half2_rn(a, b);
        }
        o[row * 16 + c8] = r;
    }
}

// ===================== fp16 mma.sync gather-GEMM conv =====================
// 512 threads / 16 warps, CTA tile 256x128, warp tile 64x32 (4M x 4N warps).
// PIPE=4 buffers, prefetch depth 2, ONE __syncthreads per stage.
// OUT_HALF: write raw fp16 output (conv1); else fp32 (+residual)
template<bool OUT_HALF>
__global__ void __launch_bounds__(NTHREADS, 1)
conv_mma_kernel(const __half* __restrict__ h,
                const int*    __restrict__ idxT,   // transposed rulebook [k][site]
                const __half* __restrict__ wt,
                const float*  __restrict__ bias,
                const float*  __restrict__ residual,
                void*         __restrict__ outv,
                float*        __restrict__ stats_part)
{
    extern __shared__ char dsm[];
    __shared__ float s_bias[C];
    __shared__ float s_st[256];

    const int tid  = threadIdx.x;
    const int warp = tid >> 5;            // 0..15
    const int lane = tid & 31;
    const int m0   = blockIdx.x * CTA_M;

    const uint32_t smA_u = smem_u32(dsm);
    const uint32_t smW_u = smA_u + PIPE * A_BYTES;

    if (tid < C) s_bias[tid] = bias[tid];
    if (tid < 256) s_st[tid] = 0.f;

    // warp tiling: 4 M-warps x 4 N-warps, warp tile 64x32
    const int mw = warp & 3;
    const int nw = warp >> 2;             // 0..3
    const int lr = lane >> 2;             // 0..7
    const int lc = lane & 3;              // 0..3
    // ldmatrix lane mapping
    const int gq = lane >> 3;
    const int gl = lane & 7;
    const int rowl = (gq & 1) * 8 + gl;
    const int ghi  = gq >> 1;

    float acc[4][4][4];
    #pragma unroll
    for (int a = 0; a < 4; a++)
        #pragma unroll
        for (int b = 0; b < 4; b++)
            #pragma unroll
            for (int q = 0; q < 4; q++) acc[a][b][q] = 0.f;

    // gather/copy split across 512 threads
    const int arow  = tid >> 1;            // A row 0..255
    const int ahalf = tid & 1;             // which 64B half of the row
    const int swAr  = (arow & 7) << 4;     // XOR swizzle term
    const int wcol  = tid & 127;
    const int wq    = tid >> 7;            // 0..3 : 32B quarter of W col

    auto issue = [&](int st, int p) {
        const int k  = st >> 1;
        const int ch = st & 1;
        int v = idxT[k * NS + m0 + arow];
        uint32_t sz = (v < 0) ? 16u : 0u;
        const __half* src = h + (v & 0x7FFFFFFF) + ch * 64 + ahalf * 32;
        uint32_t dstrow = smA_u + p * A_BYTES + arow * A_ROWB;
        #pragma unroll
        for (int j = 0; j < 4; j++)
            cp_async16(dstrow + ((((ahalf << 2) + j) << 4) ^ swAr), src + j * 8, sz);
        const __half* wsrc = wt + ((size_t)(k * 2 + ch) * C + wcol) * 64 + wq * 16;
        uint32_t wdst = smW_u + p * W_BYTES + wcol * W_STRIDEB + wq * 32;
        cp_async16(wdst,      wsrc,     16u);
        cp_async16(wdst + 16, wsrc + 8, 16u);
        CP_COMMIT();
    };

    issue(0, 0);
    issue(1, 1);

    for (int st = 0; st < NSTAGE; st++) {
        const int p = st & 3;
        if (st + 2 < NSTAGE) { issue(st + 2, (st + 2) & 3); CP_WAIT(2); }
        else if (st + 1 < NSTAGE) { CP_WAIT(1); }
        else { CP_WAIT(0); }
        __syncthreads();   // single barrier: publishes buffer p, fences buffer reuse

        const uint32_t Abase = smA_u + p * A_BYTES;
        const uint32_t Wbase = smW_u + p * W_BYTES +
                               (nw * 32 + lr) * W_STRIDEB + lc * 8;

        #pragma unroll
        for (int s = 0; s < 4; s++) {
            uint32_t af[4][4];
            #pragma unroll
            for (int mf = 0; mf < 4; mf++) {
                int row = mw * 64 + mf * 16 + rowl;
                uint32_t addr = Abase + row * A_ROWB +
                                ((((s << 1) | ghi) ^ (row & 7)) << 4);
                ldmatrix_x4(af[mf], addr);
            }
            #pragma unroll
            for (int nf = 0; nf < 4; nf++) {
                uint32_t b0, b1;
                uint32_t baddr = Wbase + nf * (8 * W_STRIDEB) + s * 32;
                asm volatile("ld.shared.v2.b32 {%0,%1}, [%2];"
                             : "=r"(b0), "=r"(b1) : "r"(baddr));
                #pragma unroll
                for (int mf = 0; mf < 4; mf++)
                    mma_f16(acc[mf][nf], af[mf], b0, b1);
            }
        }
    }

    // ---- epilogue ----
    float st_s[4][2], st_q[4][2];
    #pragma unroll
    for (int nf = 0; nf < 4; nf++) {
        st_s[nf][0] = st_s[nf][1] = 0.f;
        st_q[nf][0] = st_q[nf][1] = 0.f;
    }

    #pragma unroll
    for (int mf = 0; mf < 4; mf++) {
        int row = m0 + mw * 64 + mf * 16 + lr;
        #pragma unroll
        for (int nf = 0; nf < 4; nf++) {
            int col = nw * 32 + nf * 8 + lc * 2;
            float2 v0, v1;
            v0.x = acc[mf][nf][0] + s_bias[col];
            v0.y = acc[mf][nf][1] + s_bias[col + 1];
            v1.x = acc[mf][nf][2] + s_bias[col];
            v1.y = acc[mf][nf][3] + s_bias[col + 1];
            if (!OUT_HALF && residual) {
                float2 r0v = *(const float2*)&residual[(size_t)row * C + col];
                float2 r1v = *(const float2*)&residual[(size_t)(row + 8) * C + col];
                v0.x += r0v.x; v0.y += r0v.y;
                v1.x += r1v.x; v1.y += r1v.y;
            }
            if (stats_part) {
                st_s[nf][0] += v0.x + v1.x;
                st_s[nf][1] += v0.y + v1.y;
                st_q[nf][0] += v0.x * v0.x + v1.x * v1.x;
                st_q[nf][1] += v0.y * v0.y + v1.y * v1.y;
            }
            if (OUT_HALF) {
                __half* oh = (__half*)outv;
                *(__half2*)&oh[(size_t)row * C + col]       = __floats2half2_rn(v0.x, v0.y);
                *(__half2*)&oh[(size_t)(row + 8) * C + col] = __floats2half2_rn(v1.x, v1.y);
            } else {
                float* of = (float*)outv;
                *(float2*)&of[(size_t)row * C + col]       = v0;
                *(float2*)&of[(size_t)(row + 8) * C + col] = v1;
            }
        }
    }

    if (stats_part) {
        #pragma unroll
        for (int nf = 0; nf < 4; nf++) {
            #pragma unroll
            for (int j = 0; j < 2; j++) {
                float s = st_s[nf][j], q = st_q[nf][j];
                #pragma unroll
                for (int m = 4; m <= 16; m <<= 1) {
                    s += __shfl_xor_sync(0xFFFFFFFFu, s, m);
                    q += __shfl_xor_sync(0xFFFFFFFFu, q, m);
                }
                if (lr == 0) {
                    int col = nw * 32 + nf * 8 + lc * 2 + j;
                    atomicAdd(&s_st[col],       s);
                    atomicAdd(&s_st[col + 128], q);
                }
            }
        }
        __syncthreads();
        if (tid < 256)
            stats_part[blockIdx.x * 256 + tid] = s_st[tid];
    }
}

// ===================== launch =====================
extern "C" void kernel_launch(void* const* d_in, const int* in_sizes, int n_in,
                              void* d_out, int out_size)
{
    const float* features = (const float*)d_in[0];
    const int*   nbr_idx  = (const int*)  d_in[1];
    const int*   nbr_mask = (const int*)  d_in[2];
    const float* gamma1   = (const float*)d_in[3];
    const float* beta1    = (const float*)d_in[4];
    const float* W1       = (const float*)d_in[5];
    const float* bias1    = (const float*)d_in[6];
    const float* gamma2   = (const float*)d_in[7];
    const float* beta2    = (const float*)d_in[8];
    const float* W2       = (const float*)d_in[9];
    const float* bias2    = (const float*)d_in[10];
    float* out = (float*)d_out;

    __half *h_ptr, *yh_ptr, *wt1_ptr, *wt2_ptr;
    float *part_ptr;
    int *idx_ptr;
    cudaGetSymbolAddress((void**)&h_ptr,    g_h);
    cudaGetSymbolAddress((void**)&yh_ptr,   g_yh);
    cudaGetSymbolAddress((void**)&wt1_ptr,  g_wt1);
    cudaGetSymbolAddress((void**)&wt2_ptr,  g_wt2);
    cudaGetSymbolAddress((void**)&part_ptr, g_part);
    cudaGetSymbolAddress((void**)&idx_ptr,  g_idx);

    cudaFuncSetAttribute(conv_mma_kernel<true>,
                         cudaFuncAttributeMaxDynamicSharedMemorySize, DSMEM_TOTAL);
    cudaFuncSetAttribute(conv_mma_kernel<false>,
                         cudaFuncAttributeMaxDynamicSharedMemorySize, DSMEM_TOTAL);

    const int apply_grid = NS / 128;      // 2048 blocks

    // ---- fused prep: stats + W pack + rulebook transpose, one launch ----
    prep_kernel<<<STATS_BLKS + PACKW_BLKS + IDX_BLKS, 256>>>(
        (const float4*)features, W1, W2, nbr_idx, nbr_mask);
    reduce_finalize_kernel<<<128, 128>>>(gamma1, beta1, STATS_BLKS);
    bn_apply_pack_kernel<<<apply_grid, 256>>>((const float4*)features, (uint2*)h_ptr);
    conv_mma_kernel<true><<<NCTA, NTHREADS, DSMEM_TOTAL>>>(
        h_ptr, idx_ptr, wt1_ptr, bias1, nullptr, yh_ptr, part_ptr);

    // ---- layer 2: stats from conv1 epilogue ----
    reduce_finalize_kernel<<<128, 128>>>(gamma2, beta2, NCTA);
    bn_apply_pack_half_kernel<<<apply_grid, 256>>>((const uint4*)yh_ptr, (uint4*)h_ptr);
    conv_mma_kernel<false><<<NCTA, NTHREADS, DSMEM_TOTAL>>>(
        h_ptr, idx_ptr, wt2_ptr, bias2, features, out, nullptr);
}